// round 1
// baseline (speedup 1.0000x reference)
#include <cuda_runtime.h>
#include <math.h>
#include <stdint.h>

// Problem constants
#define LAYERS 6
#define NHEAD  16
#define DMODEL 1024
#define HDIM   64
#define BATCH  2
#define SEQ    1024
#define NTOK   (BATCH*SEQ)     // 2048
#define VOCAB  50257

// ---------------- scratch (static device globals; no runtime allocation) ----
__device__ float g_x   [NTOK*DMODEL];      // residual stream
__device__ float g_h   [NTOK*DMODEL];      // layernorm output
__device__ float g_qkv [NTOK*3*DMODEL];    // qkv projection
__device__ float g_att [NTOK*DMODEL];      // attention output
__device__ float g_ffn [NTOK*4*DMODEL];    // mlp hidden
__device__ float g_logits_fallback[(size_t)NTOK*VOCAB]; // only used if d_out can't hold logits
__device__ float g_rowloss[NTOK];

// ---------------- embedding: x = wte[idx] + wpe[t] ---------------------------
__global__ void embed_k(const int* __restrict__ idx,
                        const float* __restrict__ wte,
                        const float* __restrict__ wpe,
                        float* __restrict__ x)
{
    int n = blockIdx.x;
    int tok = idx[n];
    int t = n % SEQ;
    const float4* a = (const float4*)(wte + (size_t)tok * DMODEL);
    const float4* p = (const float4*)(wpe + (size_t)t   * DMODEL);
    float4* o = (float4*)(x + (size_t)n * DMODEL);
    for (int i = threadIdx.x; i < DMODEL/4; i += blockDim.x) {
        float4 u = a[i], v = p[i];
        o[i] = make_float4(u.x+v.x, u.y+v.y, u.z+v.z, u.w+v.w);
    }
}

// ---------------- layernorm (row = 1024) -------------------------------------
__global__ void __launch_bounds__(256) ln_k(const float* __restrict__ x,
                                            const float* __restrict__ w,
                                            const float* __restrict__ b,
                                            float* __restrict__ out)
{
    int n = blockIdx.x;
    const float* row = x + (size_t)n * DMODEL;
    float s = 0.f, ss = 0.f;
    for (int i = threadIdx.x; i < DMODEL/4; i += 256) {
        float4 v = ((const float4*)row)[i];
        s  += v.x + v.y + v.z + v.w;
        ss += v.x*v.x + v.y*v.y + v.z*v.z + v.w*v.w;
    }
    #pragma unroll
    for (int o = 16; o; o >>= 1) {
        s  += __shfl_xor_sync(0xffffffffu, s,  o);
        ss += __shfl_xor_sync(0xffffffffu, ss, o);
    }
    __shared__ float sm[8], sm2[8];
    int wid = threadIdx.x >> 5;
    if ((threadIdx.x & 31) == 0) { sm[wid] = s; sm2[wid] = ss; }
    __syncthreads();
    if (threadIdx.x < 32) {
        s  = (threadIdx.x < 8) ? sm [threadIdx.x] : 0.f;
        ss = (threadIdx.x < 8) ? sm2[threadIdx.x] : 0.f;
        #pragma unroll
        for (int o = 4; o; o >>= 1) {
            s  += __shfl_xor_sync(0xffffffffu, s,  o);
            ss += __shfl_xor_sync(0xffffffffu, ss, o);
        }
        if (threadIdx.x == 0) { sm[0] = s; sm2[0] = ss; }
    }
    __syncthreads();
    float mean = sm[0] * (1.0f/DMODEL);
    float var  = sm2[0] * (1.0f/DMODEL) - mean*mean;
    float inv  = rsqrtf(var + 1e-5f);
    float* orow = out + (size_t)n * DMODEL;
    for (int i = threadIdx.x; i < DMODEL/4; i += 256) {
        float4 v  = ((const float4*)row)[i];
        float4 gw = ((const float4*)w)[i];
        float4 gb = ((const float4*)b)[i];
        float4 r;
        r.x = (v.x - mean)*inv*gw.x + gb.x;
        r.y = (v.y - mean)*inv*gw.y + gb.y;
        r.z = (v.z - mean)*inv*gw.z + gb.z;
        r.w = (v.w - mean)*inv*gw.w + gb.w;
        ((float4*)orow)[i] = r;
    }
}

// ---------------- generic NT GEMM: C[M,N] = A[M,K] * B[N,K]^T (+epi) ---------
// M assumed multiple of 128. K multiple of 16. N arbitrary (guarded).
enum { EPI_NONE = 0, EPI_GELU = 1, EPI_RESID = 2 };

template<int EPI>
__global__ void __launch_bounds__(256) gemm_nt(
    const float* __restrict__ A, const float* __restrict__ B,
    const float* __restrict__ bias, const float* __restrict__ Rres,
    float* __restrict__ C, int M, int N, int K)
{
    __shared__ float As[16][128];
    __shared__ float Bs[16][128];
    const int tid = threadIdx.x;
    const int bm = blockIdx.y * 128;
    const int bn = blockIdx.x * 128;
    const int ty = tid >> 4, tx = tid & 15;
    float acc[8][8] = {};
    for (int k0 = 0; k0 < K; k0 += 16) {
        #pragma unroll
        for (int i = 0; i < 2; i++) {
            int f  = tid + i*256;           // 0..511
            int r  = f >> 2;                // tile row 0..127
            int c4 = (f & 3) << 2;          // 0,4,8,12
            float4 va = *(const float4*)(A + (size_t)(bm + r)*K + k0 + c4);
            As[c4+0][r] = va.x; As[c4+1][r] = va.y; As[c4+2][r] = va.z; As[c4+3][r] = va.w;
            int gb = bn + r;
            float4 vb = (gb < N) ? *(const float4*)(B + (size_t)gb*K + k0 + c4)
                                 : make_float4(0.f,0.f,0.f,0.f);
            Bs[c4+0][r] = vb.x; Bs[c4+1][r] = vb.y; Bs[c4+2][r] = vb.z; Bs[c4+3][r] = vb.w;
        }
        __syncthreads();
        #pragma unroll
        for (int kk = 0; kk < 16; kk++) {
            float4 a0 = *(const float4*)&As[kk][ty*8];
            float4 a1 = *(const float4*)&As[kk][ty*8 + 4];
            float4 b0 = *(const float4*)&Bs[kk][tx*8];
            float4 b1 = *(const float4*)&Bs[kk][tx*8 + 4];
            float a[8] = {a0.x,a0.y,a0.z,a0.w,a1.x,a1.y,a1.z,a1.w};
            float b[8] = {b0.x,b0.y,b0.z,b0.w,b1.x,b1.y,b1.z,b1.w};
            #pragma unroll
            for (int i = 0; i < 8; i++)
                #pragma unroll
                for (int j = 0; j < 8; j++)
                    acc[i][j] += a[i]*b[j];
        }
        __syncthreads();
    }
    #pragma unroll
    for (int i = 0; i < 8; i++) {
        size_t row = bm + ty*8 + i;
        #pragma unroll
        for (int j = 0; j < 8; j++) {
            int col = bn + tx*8 + j;
            if (col < N) {
                float v = acc[i][j];
                if (bias) v += bias[col];
                if (EPI == EPI_GELU)  v = 0.5f*v*(1.0f + erff(v*0.70710678118654752f));
                if (EPI == EPI_RESID) v += Rres[row*(size_t)N + col];
                C[row*(size_t)N + col] = v;
            }
        }
    }
}

// ---------------- flash attention: Q tile 64, K tile 32, hd=64 ---------------
#define QT 64
#define KTI 32

__global__ void __launch_bounds__(256) attn_k(const float* __restrict__ qkv,
                                              float* __restrict__ y)
{
    __shared__ float Qs[QT][HDIM+4];
    __shared__ float Kt[HDIM][KTI+4];   // transposed: [d][j]
    __shared__ float Vs[KTI][HDIM+4];
    __shared__ float Ss[QT][KTI+4];

    const int bh = blockIdx.y;          // 0..31
    const int b = bh >> 4, h = bh & 15;
    const int q0 = blockIdx.x * QT;
    const int tid = threadIdx.x;
    const int r = tid >> 2;             // query row 0..63
    const int quad = tid & 3;

    // load Q tile (pre-scaled by 1/sqrt(64))
    for (int f = tid; f < QT*HDIM/4; f += 256) {
        int qi = f >> 4;
        int c4 = (f & 15) << 2;
        float4 v = *(const float4*)(qkv + (size_t)(b*SEQ + q0 + qi)*3*DMODEL + h*HDIM + c4);
        Qs[qi][c4+0] = v.x*0.125f; Qs[qi][c4+1] = v.y*0.125f;
        Qs[qi][c4+2] = v.z*0.125f; Qs[qi][c4+3] = v.w*0.125f;
    }

    float m_r = -1e30f, l_r = 0.f;
    float acc[16];
    #pragma unroll
    for (int i = 0; i < 16; i++) acc[i] = 0.f;

    for (int k0 = 0; k0 < q0 + QT; k0 += KTI) {
        __syncthreads();   // protect Kt/Vs before overwrite (also orders Qs on iter 0)
        for (int f = tid; f < KTI*HDIM/4; f += 256) {
            int j  = f >> 4;            // 0..31
            int c4 = (f & 15) << 2;
            size_t rowoff = (size_t)(b*SEQ + k0 + j)*3*DMODEL + h*HDIM + c4;
            float4 kv = *(const float4*)(qkv + DMODEL   + rowoff);
            Kt[c4+0][j] = kv.x; Kt[c4+1][j] = kv.y; Kt[c4+2][j] = kv.z; Kt[c4+3][j] = kv.w;
            float4 vv = *(const float4*)(qkv + 2*DMODEL + rowoff);
            *(float4*)&Vs[j][c4] = vv;
        }
        __syncthreads();

        // scores for j in quad*8 .. quad*8+7
        float s[8];
        #pragma unroll
        for (int jj = 0; jj < 8; jj++) s[jj] = 0.f;
        #pragma unroll 4
        for (int d = 0; d < HDIM; d++) {
            float qv = Qs[r][d];
            float4 k0v = *(const float4*)&Kt[d][quad*8];
            float4 k1v = *(const float4*)&Kt[d][quad*8 + 4];
            s[0] += qv*k0v.x; s[1] += qv*k0v.y; s[2] += qv*k0v.z; s[3] += qv*k0v.w;
            s[4] += qv*k1v.x; s[5] += qv*k1v.y; s[6] += qv*k1v.z; s[7] += qv*k1v.w;
        }
        // causal mask
        #pragma unroll
        for (int jj = 0; jj < 8; jj++) {
            int kj = k0 + quad*8 + jj;
            if (kj > q0 + r) s[jj] = -1e30f;
        }
        // online softmax (per row; 4 lanes/row butterfly)
        float mx = s[0];
        #pragma unroll
        for (int jj = 1; jj < 8; jj++) mx = fmaxf(mx, s[jj]);
        mx = fmaxf(mx, __shfl_xor_sync(0xffffffffu, mx, 1));
        mx = fmaxf(mx, __shfl_xor_sync(0xffffffffu, mx, 2));
        float newm = fmaxf(m_r, mx);
        float corr = __expf(m_r - newm);
        float psum = 0.f;
        #pragma unroll
        for (int jj = 0; jj < 8; jj++) { s[jj] = __expf(s[jj] - newm); psum += s[jj]; }
        psum += __shfl_xor_sync(0xffffffffu, psum, 1);
        psum += __shfl_xor_sync(0xffffffffu, psum, 2);
        l_r = l_r * corr + psum;
        m_r = newm;
        #pragma unroll
        for (int dd = 0; dd < 16; dd++) acc[dd] *= corr;
        #pragma unroll
        for (int jj = 0; jj < 8; jj++) Ss[r][quad*8 + jj] = s[jj];
        __syncwarp();

        // O[r][quad*16+dd] += sum_j p[r][j] * V[j][quad*16+dd]
        #pragma unroll 4
        for (int j = 0; j < KTI; j++) {
            float p = Ss[r][j];
            float4 v0 = *(const float4*)&Vs[j][quad*16];
            float4 v1 = *(const float4*)&Vs[j][quad*16 + 4];
            float4 v2 = *(const float4*)&Vs[j][quad*16 + 8];
            float4 v3 = *(const float4*)&Vs[j][quad*16 + 12];
            acc[0]  += p*v0.x; acc[1]  += p*v0.y; acc[2]  += p*v0.z; acc[3]  += p*v0.w;
            acc[4]  += p*v1.x; acc[5]  += p*v1.y; acc[6]  += p*v1.z; acc[7]  += p*v1.w;
            acc[8]  += p*v2.x; acc[9]  += p*v2.y; acc[10] += p*v2.z; acc[11] += p*v2.w;
            acc[12] += p*v3.x; acc[13] += p*v3.y; acc[14] += p*v3.z; acc[15] += p*v3.w;
        }
    }

    float invl = 1.0f / l_r;
    float* out = y + (size_t)(b*SEQ + q0 + r)*DMODEL + h*HDIM + quad*16;
    #pragma unroll
    for (int dd = 0; dd < 16; dd++) out[dd] = acc[dd] * invl;
}

// ---------------- per-row loss: lse - logit[target] --------------------------
__global__ void __launch_bounds__(256) rowloss_k(const float* __restrict__ logits,
                                                 const int* __restrict__ tgt,
                                                 float* __restrict__ rowloss)
{
    int n = blockIdx.x;
    const float* row = logits + (size_t)n * VOCAB;
    float m = -1e30f, ssum = 0.f;
    for (int i = threadIdx.x; i < VOCAB; i += 256) {
        float v = row[i];
        if (v > m) { ssum *= __expf(m - v); m = v; }
        ssum += __expf(v - m);
    }
    #pragma unroll
    for (int o = 16; o; o >>= 1) {
        float m2 = __shfl_xor_sync(0xffffffffu, m, o);
        float s2 = __shfl_xor_sync(0xffffffffu, ssum, o);
        float M  = fmaxf(m, m2);
        ssum = ssum*__expf(m - M) + s2*__expf(m2 - M);
        m = M;
    }
    __shared__ float smm[8], sms[8];
    int wid = threadIdx.x >> 5;
    if ((threadIdx.x & 31) == 0) { smm[wid] = m; sms[wid] = ssum; }
    __syncthreads();
    if (threadIdx.x == 0) {
        float M = smm[0], S = sms[0];
        for (int i = 1; i < 8; i++) {
            float M2 = fmaxf(M, smm[i]);
            S = S*__expf(M - M2) + sms[i]*__expf(smm[i] - M2);
            M = M2;
        }
        float lse = M + logf(S);
        rowloss[n] = lse - row[tgt[n]];
    }
}

__global__ void finalize_k(const float* __restrict__ rowloss, float* __restrict__ out_loss)
{
    float s = 0.f;
    for (int i = threadIdx.x; i < NTOK; i += 256) s += rowloss[i];
    #pragma unroll
    for (int o = 16; o; o >>= 1) s += __shfl_xor_sync(0xffffffffu, s, o);
    __shared__ float sm[8];
    int wid = threadIdx.x >> 5;
    if ((threadIdx.x & 31) == 0) sm[wid] = s;
    __syncthreads();
    if (threadIdx.x == 0) {
        float t = 0.f;
        for (int i = 0; i < 8; i++) t += sm[i];
        *out_loss = t * (1.0f/NTOK);
    }
}

// ---------------- launch -----------------------------------------------------
extern "C" void kernel_launch(void* const* d_in, const int* in_sizes, int n_in,
                              void* d_out, int out_size)
{
    const int*   idx     = (const int*)  d_in[0];
    const int*   targets = (const int*)  d_in[1];
    const float* wte     = (const float*)d_in[2];
    const float* wpe     = (const float*)d_in[3];
    const float* ln1_w   = (const float*)d_in[4];
    const float* ln1_b   = (const float*)d_in[5];
    const float* attn_w  = (const float*)d_in[6];
    const float* attn_b  = (const float*)d_in[7];
    const float* proj_w  = (const float*)d_in[8];
    const float* proj_b  = (const float*)d_in[9];
    const float* ln2_w   = (const float*)d_in[10];
    const float* ln2_b   = (const float*)d_in[11];
    const float* fc_w    = (const float*)d_in[12];
    const float* fc_b    = (const float*)d_in[13];
    const float* fcp_w   = (const float*)d_in[14];
    const float* fcp_b   = (const float*)d_in[15];
    const float* lnf_w   = (const float*)d_in[16];
    const float* lnf_b   = (const float*)d_in[17];

    float *px, *ph, *pqkv, *patt, *pffn, *plogfb, *prl;
    cudaGetSymbolAddress((void**)&px,    g_x);
    cudaGetSymbolAddress((void**)&ph,    g_h);
    cudaGetSymbolAddress((void**)&pqkv,  g_qkv);
    cudaGetSymbolAddress((void**)&patt,  g_att);
    cudaGetSymbolAddress((void**)&pffn,  g_ffn);
    cudaGetSymbolAddress((void**)&plogfb,g_logits_fallback);
    cudaGetSymbolAddress((void**)&prl,   g_rowloss);

    const long long LOGN = (long long)NTOK * VOCAB;
    float* logits_ptr;
    float* loss_ptr = nullptr;
    if ((long long)out_size >= LOGN) {
        logits_ptr = (float*)d_out;
        if ((long long)out_size > LOGN) loss_ptr = (float*)d_out + LOGN;
    } else {
        logits_ptr = plogfb;
        loss_ptr = (float*)d_out;   // loss-only output
    }

    embed_k<<<NTOK, 256>>>(idx, wte, wpe, px);

    dim3 gq (3*DMODEL/128, NTOK/128);   // 24 x 16
    dim3 gp (DMODEL/128,   NTOK/128);   //  8 x 16
    dim3 gf (4*DMODEL/128, NTOK/128);   // 32 x 16
    dim3 gv ((VOCAB+127)/128, NTOK/128);// 393 x 16
    dim3 ga (SEQ/QT, BATCH*NHEAD);      // 16 x 32

    for (int l = 0; l < LAYERS; l++) {
        ln_k<<<NTOK, 256>>>(px, ln1_w + (size_t)l*DMODEL, ln1_b + (size_t)l*DMODEL, ph);
        gemm_nt<EPI_NONE><<<gq, 256>>>(ph, attn_w + (size_t)l*3*DMODEL*DMODEL,
                                       attn_b + (size_t)l*3*DMODEL, nullptr,
                                       pqkv, NTOK, 3*DMODEL, DMODEL);
        attn_k<<<ga, 256>>>(pqkv, patt);
        gemm_nt<EPI_RESID><<<gp, 256>>>(patt, proj_w + (size_t)l*DMODEL*DMODEL,
                                        proj_b + (size_t)l*DMODEL, px,
                                        px, NTOK, DMODEL, DMODEL);
        ln_k<<<NTOK, 256>>>(px, ln2_w + (size_t)l*DMODEL, ln2_b + (size_t)l*DMODEL, ph);
        gemm_nt<EPI_GELU><<<gf, 256>>>(ph, fc_w + (size_t)l*4*DMODEL*DMODEL,
                                       fc_b + (size_t)l*4*DMODEL, nullptr,
                                       pffn, NTOK, 4*DMODEL, DMODEL);
        gemm_nt<EPI_RESID><<<gp, 256>>>(pffn, fcp_w + (size_t)l*DMODEL*4*DMODEL,
                                        fcp_b + (size_t)l*DMODEL, px,
                                        px, NTOK, DMODEL, 4*DMODEL);
    }

    ln_k<<<NTOK, 256>>>(px, lnf_w, lnf_b, ph);
    gemm_nt<EPI_NONE><<<gv, 256>>>(ph, wte, nullptr, nullptr,
                                   logits_ptr, NTOK, VOCAB, DMODEL);

    if (loss_ptr) {
        rowloss_k<<<NTOK, 256>>>(logits_ptr, targets, prl);
        finalize_k<<<1, 256>>>(prl, loss_ptr);
    }
}

// round 4
// speedup vs baseline: 3.4052x; 3.4052x over previous
#include <cuda_runtime.h>
#include <math.h>
#include <stdint.h>

// Problem constants
#define LAYERS 6
#define NHEAD  16
#define DMODEL 1024
#define HDIM   64
#define BATCH  2
#define SEQ    1024
#define NTOK   (BATCH*SEQ)     // 2048
#define VOCAB  50257

// ---------------- scratch ----------------------------------------------------
__device__ float g_x   [NTOK*DMODEL];
__device__ float g_h   [NTOK*DMODEL];
__device__ float g_qkv [NTOK*3*DMODEL];
__device__ float g_att [NTOK*DMODEL];
__device__ float g_ffn [NTOK*4*DMODEL];
__device__ float g_logits_fallback[(size_t)NTOK*VOCAB];
__device__ float g_rowloss[NTOK];

// ---------------- PTX helpers (sm_80-portable only) --------------------------
__device__ __forceinline__ uint32_t smem_to_u32(const void* p) {
    uint32_t a;
    asm("{ .reg .u64 t; cvta.to.shared.u64 t, %1; cvt.u32.u64 %0, t; }" : "=r"(a) : "l"(p));
    return a;
}
__device__ __forceinline__ void cp_async16(uint32_t dst, const void* src, int srcsize) {
    asm volatile("cp.async.cg.shared.global [%0], [%1], 16, %2;\n"
                 :: "r"(dst), "l"(src), "r"(srcsize) : "memory");
}
#define CP_COMMIT() asm volatile("cp.async.commit_group;" ::: "memory")

#define LDSM_X4(r, a) \
    asm volatile("ldmatrix.sync.aligned.m8n8.x4.shared.b16 {%0,%1,%2,%3}, [%4];" \
        : "=r"((r)[0]), "=r"((r)[1]), "=r"((r)[2]), "=r"((r)[3]) : "r"(a))

#define MMA_TF32(d, a, b) \
    asm volatile("mma.sync.aligned.m16n8k8.row.col.f32.tf32.tf32.f32 " \
        "{%0,%1,%2,%3}, {%4,%5,%6,%7}, {%8,%9}, {%0,%1,%2,%3};" \
        : "+f"((d)[0]), "+f"((d)[1]), "+f"((d)[2]), "+f"((d)[3]) \
        : "r"((a)[0]), "r"((a)[1]), "r"((a)[2]), "r"((a)[3]), "r"((b)[0]), "r"((b)[1]))

__device__ __forceinline__ uint32_t cvt_tf32(uint32_t x) {
    uint32_t y;
    asm("cvt.rna.tf32.f32 %0, %1;" : "=r"(y) : "f"(__uint_as_float(x)));
    return y;
}

// ---------------- tf32 mma.sync NT GEMM: C[M,N] = A[M,K]*B[N,K]^T (+epi) -----
// 128x128 CTA tile, BK=32, 8 warps (2x4), warp tile 64x32, 3-stage cp.async.
enum { EPI_NONE = 0, EPI_GELU = 1, EPI_RESID = 2 };

#define GBM 128
#define GBK 32
#define GSTAGES 3
#define GSTAGE_BYTES (GBM*GBK*4)                 // 16384
#define GT_SMEM (1024 + 2*GSTAGES*GSTAGE_BYTES)  // 99328

// row r (0..127), chunk c (0..7 float4s within the 32-float row), XOR swizzle
__device__ __forceinline__ uint32_t sw_off(int r, int c) {
    return (uint32_t)(r * 128 + ((c ^ (r & 7)) << 4));
}

template<int EPI>
__global__ void __launch_bounds__(256, 2) gemm_tc(
    const float* __restrict__ A, const float* __restrict__ B,
    const float* __restrict__ bias, const float* __restrict__ Rres,
    float* __restrict__ C, int M, int N, int K)
{
    extern __shared__ char dsm[];
    const int tid  = threadIdx.x;
    const int wid  = tid >> 5;
    const int lane = tid & 31;
    const int wm = wid >> 2;            // 0..1
    const int wn = wid & 3;             // 0..3
    const int bm = blockIdx.y * 128;
    const int bn = blockIdx.x * 128;

    uint32_t sbase = (smem_to_u32(dsm) + 1023u) & ~1023u;
    uint32_t aStage0 = sbase;
    uint32_t bStage0 = sbase + GSTAGES * GSTAGE_BYTES;

    const int T = K / GBK;

    auto load_tile = [&](int kt, int slot) {
        int k0 = kt * GBK;
        uint32_t aB = aStage0 + slot * GSTAGE_BYTES;
        uint32_t bB = bStage0 + slot * GSTAGE_BYTES;
        #pragma unroll
        for (int u = 0; u < 4; u++) {
            int f = tid + u * 256;       // 0..1023
            int r = f >> 3, c = f & 7;
            cp_async16(aB + sw_off(r, c), A + (size_t)(bm + r) * K + k0 + c * 4, 16);
            int gb = bn + r;
            const float* bsrc = B + (size_t)(gb < N ? gb : 0) * K + k0 + c * 4;
            cp_async16(bB + sw_off(r, c), bsrc, gb < N ? 16 : 0);
        }
        CP_COMMIT();
    };

    float acc[4][4][4];
    #pragma unroll
    for (int i = 0; i < 4; i++)
        #pragma unroll
        for (int j = 0; j < 4; j++)
            #pragma unroll
            for (int v = 0; v < 4; v++) acc[i][j][v] = 0.f;

    load_tile(0, 0);
    load_tile(1, 1);
    load_tile(2, 2);

    for (int kt = 0; kt < T; kt++) {
        if (kt < T - 2)       asm volatile("cp.async.wait_group 2;" ::: "memory");
        else if (kt == T - 2) asm volatile("cp.async.wait_group 1;" ::: "memory");
        else                  asm volatile("cp.async.wait_group 0;" ::: "memory");
        __syncthreads();

        int slot = kt % GSTAGES;
        uint32_t aS = aStage0 + slot * GSTAGE_BYTES;
        uint32_t bS = bStage0 + slot * GSTAGE_BYTES;

        #pragma unroll
        for (int kk = 0; kk < 4; kk++) {
            uint32_t af[4][4];
            uint32_t bf[4][2];
            #pragma unroll
            for (int mb = 0; mb < 4; mb++) {
                int row = wm * 64 + mb * 16 + (lane & 15);
                int chunk = kk * 2 + (lane >> 4);
                LDSM_X4(af[mb], aS + row * 128 + ((chunk ^ (row & 7)) << 4));
            }
            #pragma unroll
            for (int p = 0; p < 2; p++) {
                uint32_t r4[4];
                int n = wn * 32 + p * 16 + (lane & 7) + ((lane >> 4) << 3);
                int chunk = kk * 2 + ((lane >> 3) & 1);
                LDSM_X4(r4, bS + n * 128 + ((chunk ^ (n & 7)) << 4));
                bf[p*2  ][0] = r4[0]; bf[p*2  ][1] = r4[1];
                bf[p*2+1][0] = r4[2]; bf[p*2+1][1] = r4[3];
            }
            // round-to-nearest tf32 (avoids HMMA truncation bias ~2^-10)
            #pragma unroll
            for (int mb = 0; mb < 4; mb++)
                #pragma unroll
                for (int v = 0; v < 4; v++) af[mb][v] = cvt_tf32(af[mb][v]);
            #pragma unroll
            for (int nb = 0; nb < 4; nb++) {
                bf[nb][0] = cvt_tf32(bf[nb][0]);
                bf[nb][1] = cvt_tf32(bf[nb][1]);
            }
            #pragma unroll
            for (int mb = 0; mb < 4; mb++)
                #pragma unroll
                for (int nb = 0; nb < 4; nb++)
                    MMA_TF32(acc[mb][nb], af[mb], bf[nb]);
        }
        __syncthreads();
        if (kt + GSTAGES < T) load_tile(kt + GSTAGES, slot);
    }

    // epilogue (alignment-safe: N may be odd, e.g. VOCAB=50257)
    #pragma unroll
    for (int mb = 0; mb < 4; mb++) {
        int r0 = bm + wm * 64 + mb * 16 + (lane >> 2);
        #pragma unroll
        for (int nb = 0; nb < 4; nb++) {
            int col = bn + wn * 32 + nb * 8 + (lane & 3) * 2;
            #pragma unroll
            for (int half = 0; half < 2; half++) {
                size_t row = (size_t)(r0 + half * 8);
                float v0 = acc[mb][nb][half*2 + 0];
                float v1 = acc[mb][nb][half*2 + 1];
                size_t base = row * (size_t)N + col;
                if (col + 1 < N) {
                    if (bias) { v0 += bias[col]; v1 += bias[col+1]; }
                    if (EPI == EPI_GELU) {
                        v0 = 0.5f*v0*(1.0f + erff(v0*0.70710678118654752f));
                        v1 = 0.5f*v1*(1.0f + erff(v1*0.70710678118654752f));
                    }
                    if (EPI == EPI_RESID) {
                        if ((base & 1) == 0) {
                            float2 rr = *(const float2*)(Rres + base);
                            v0 += rr.x; v1 += rr.y;
                        } else {
                            v0 += Rres[base]; v1 += Rres[base + 1];
                        }
                    }
                    if ((base & 1) == 0) {
                        *(float2*)(C + base) = make_float2(v0, v1);
                    } else {
                        C[base] = v0; C[base + 1] = v1;
                    }
                } else if (col < N) {
                    if (bias) v0 += bias[col];
                    if (EPI == EPI_GELU) v0 = 0.5f*v0*(1.0f + erff(v0*0.70710678118654752f));
                    if (EPI == EPI_RESID) v0 += Rres[base];
                    C[base] = v0;
                }
            }
        }
    }
}

// ---------------- embedding --------------------------------------------------
__global__ void embed_k(const int* __restrict__ idx,
                        const float* __restrict__ wte,
                        const float* __restrict__ wpe,
                        float* __restrict__ x)
{
    int n = blockIdx.x;
    int tok = idx[n];
    int t = n % SEQ;
    const float4* a = (const float4*)(wte + (size_t)tok * DMODEL);
    const float4* p = (const float4*)(wpe + (size_t)t   * DMODEL);
    float4* o = (float4*)(x + (size_t)n * DMODEL);
    for (int i = threadIdx.x; i < DMODEL/4; i += blockDim.x) {
        float4 u = a[i], v = p[i];
        o[i] = make_float4(u.x+v.x, u.y+v.y, u.z+v.z, u.w+v.w);
    }
}

// ---------------- layernorm --------------------------------------------------
__global__ void __launch_bounds__(256) ln_k(const float* __restrict__ x,
                                            const float* __restrict__ w,
                                            const float* __restrict__ b,
                                            float* __restrict__ out)
{
    int n = blockIdx.x;
    const float* row = x + (size_t)n * DMODEL;
    float s = 0.f, ss = 0.f;
    for (int i = threadIdx.x; i < DMODEL/4; i += 256) {
        float4 v = ((const float4*)row)[i];
        s  += v.x + v.y + v.z + v.w;
        ss += v.x*v.x + v.y*v.y + v.z*v.z + v.w*v.w;
    }
    #pragma unroll
    for (int o = 16; o; o >>= 1) {
        s  += __shfl_xor_sync(0xffffffffu, s,  o);
        ss += __shfl_xor_sync(0xffffffffu, ss, o);
    }
    __shared__ float sm[8], sm2[8];
    int wid = threadIdx.x >> 5;
    if ((threadIdx.x & 31) == 0) { sm[wid] = s; sm2[wid] = ss; }
    __syncthreads();
    if (threadIdx.x < 32) {
        s  = (threadIdx.x < 8) ? sm [threadIdx.x] : 0.f;
        ss = (threadIdx.x < 8) ? sm2[threadIdx.x] : 0.f;
        #pragma unroll
        for (int o = 4; o; o >>= 1) {
            s  += __shfl_xor_sync(0xffffffffu, s,  o);
            ss += __shfl_xor_sync(0xffffffffu, ss, o);
        }
        if (threadIdx.x == 0) { sm[0] = s; sm2[0] = ss; }
    }
    __syncthreads();
    float mean = sm[0] * (1.0f/DMODEL);
    float var  = sm2[0] * (1.0f/DMODEL) - mean*mean;
    float inv  = rsqrtf(var + 1e-5f);
    float* orow = out + (size_t)n * DMODEL;
    for (int i = threadIdx.x; i < DMODEL/4; i += 256) {
        float4 v  = ((const float4*)row)[i];
        float4 gw = ((const float4*)w)[i];
        float4 gb = ((const float4*)b)[i];
        float4 r;
        r.x = (v.x - mean)*inv*gw.x + gb.x;
        r.y = (v.y - mean)*inv*gw.y + gb.y;
        r.z = (v.z - mean)*inv*gw.z + gb.z;
        r.w = (v.w - mean)*inv*gw.w + gb.w;
        ((float4*)orow)[i] = r;
    }
}

// ---------------- flash attention: 4 query rows / thread ---------------------
#define AQT 128
#define AKT 32
#define A_QOFF 0        // Qs[128][68]
#define A_KOFF 8704     // Kt[64][36]
#define A_VOFF 11008    // Vs[32][68]
#define A_SOFF 13184    // Ss[128][33]
#define A_SMEM_FLOATS 17408

__global__ void __launch_bounds__(128) attn_k(const float* __restrict__ qkv,
                                              float* __restrict__ y)
{
    extern __shared__ float smf[];
    float* Qs = smf + A_QOFF;
    float* Kt = smf + A_KOFF;
    float* Vs = smf + A_VOFF;
    float* Ss = smf + A_SOFF;

    const int bh = blockIdx.y;
    const int b = bh >> 4, h = bh & 15;
    const int q0 = blockIdx.x * AQT;
    const int tid = threadIdx.x;
    const int rb = tid >> 2;
    const int quad = tid & 3;

    #pragma unroll
    for (int u = 0; u < 16; u++) {
        int f = tid + u*128;
        int qi = f >> 4; int c4 = (f & 15) << 2;
        float4 v = *(const float4*)(qkv + (size_t)(b*SEQ + q0 + qi)*3*DMODEL + h*HDIM + c4);
        *(float4*)(Qs + qi*68 + c4) =
            make_float4(v.x*0.125f, v.y*0.125f, v.z*0.125f, v.w*0.125f);
    }

    float m[4], l[4], acc[4][16];
    #pragma unroll
    for (int k = 0; k < 4; k++) {
        m[k] = -1e30f; l[k] = 0.f;
        #pragma unroll
        for (int d = 0; d < 16; d++) acc[k][d] = 0.f;
    }

    const int kend = q0 + AQT;
    for (int k0 = 0; k0 < kend; k0 += AKT) {
        __syncthreads();
        #pragma unroll
        for (int u = 0; u < 4; u++) {
            int f = tid + u*128;
            int j = f >> 4; int c4 = (f & 15) << 2;
            size_t ro = (size_t)(b*SEQ + k0 + j)*3*DMODEL + h*HDIM + c4;
            float4 kv = *(const float4*)(qkv + DMODEL + ro);
            Kt[(c4+0)*36 + j] = kv.x; Kt[(c4+1)*36 + j] = kv.y;
            Kt[(c4+2)*36 + j] = kv.z; Kt[(c4+3)*36 + j] = kv.w;
            *(float4*)(Vs + j*68 + c4) = *(const float4*)(qkv + 2*DMODEL + ro);
        }
        __syncthreads();

        float s[4][8];
        #pragma unroll
        for (int k = 0; k < 4; k++)
            #pragma unroll
            for (int jj = 0; jj < 8; jj++) s[k][jj] = 0.f;

        #pragma unroll 8
        for (int d = 0; d < HDIM; d++) {
            float4 ka = *(const float4*)(Kt + d*36 + quad*8);
            float4 kb = *(const float4*)(Kt + d*36 + quad*8 + 4);
            #pragma unroll
            for (int k = 0; k < 4; k++) {
                float qv = Qs[(rb + 32*k)*68 + d];
                s[k][0] += qv*ka.x; s[k][1] += qv*ka.y; s[k][2] += qv*ka.z; s[k][3] += qv*ka.w;
                s[k][4] += qv*kb.x; s[k][5] += qv*kb.y; s[k][6] += qv*kb.z; s[k][7] += qv*kb.w;
            }
        }

        #pragma unroll
        for (int k = 0; k < 4; k++) {
            int qrow = q0 + rb + 32*k;
            #pragma unroll
            for (int jj = 0; jj < 8; jj++) {
                int kj = k0 + quad*8 + jj;
                if (kj > qrow) s[k][jj] = -1e30f;
            }
            float mx = s[k][0];
            #pragma unroll
            for (int jj = 1; jj < 8; jj++) mx = fmaxf(mx, s[k][jj]);
            mx = fmaxf(mx, __shfl_xor_sync(0xffffffffu, mx, 1));
            mx = fmaxf(mx, __shfl_xor_sync(0xffffffffu, mx, 2));
            float nm = fmaxf(m[k], mx);
            float corr = __expf(m[k] - nm);
            float ps = 0.f;
            #pragma unroll
            for (int jj = 0; jj < 8; jj++) { s[k][jj] = __expf(s[k][jj] - nm); ps += s[k][jj]; }
            ps += __shfl_xor_sync(0xffffffffu, ps, 1);
            ps += __shfl_xor_sync(0xffffffffu, ps, 2);
            l[k] = l[k]*corr + ps;
            m[k] = nm;
            #pragma unroll
            for (int dd = 0; dd < 16; dd++) acc[k][dd] *= corr;
            #pragma unroll
            for (int jj = 0; jj < 8; jj++) Ss[(rb + 32*k)*33 + quad*8 + jj] = s[k][jj];
        }
        __syncwarp();

        #pragma unroll 4
        for (int j = 0; j < AKT; j++) {
            float4 v0 = *(const float4*)(Vs + j*68 + quad*16);
            float4 v1 = *(const float4*)(Vs + j*68 + quad*16 + 4);
            float4 v2 = *(const float4*)(Vs + j*68 + quad*16 + 8);
            float4 v3 = *(const float4*)(Vs + j*68 + quad*16 + 12);
            #pragma unroll
            for (int k = 0; k < 4; k++) {
                float p = Ss[(rb + 32*k)*33 + j];
                acc[k][0]  += p*v0.x; acc[k][1]  += p*v0.y; acc[k][2]  += p*v0.z; acc[k][3]  += p*v0.w;
                acc[k][4]  += p*v1.x; acc[k][5]  += p*v1.y; acc[k][6]  += p*v1.z; acc[k][7]  += p*v1.w;
                acc[k][8]  += p*v2.x; acc[k][9]  += p*v2.y; acc[k][10] += p*v2.z; acc[k][11] += p*v2.w;
                acc[k][12] += p*v3.x; acc[k][13] += p*v3.y; acc[k][14] += p*v3.z; acc[k][15] += p*v3.w;
            }
        }
        __syncwarp();
    }

    #pragma unroll
    for (int k = 0; k < 4; k++) {
        float inv = 1.0f / l[k];
        int row = q0 + rb + 32*k;
        float* out = y + (size_t)(b*SEQ + row)*DMODEL + h*HDIM + quad*16;
        #pragma unroll
        for (int g = 0; g < 4; g++)
            ((float4*)out)[g] = make_float4(acc[k][g*4]*inv, acc[k][g*4+1]*inv,
                                            acc[k][g*4+2]*inv, acc[k][g*4+3]*inv);
    }
}

// ---------------- loss -------------------------------------------------------
__global__ void __launch_bounds__(256) rowloss_k(const float* __restrict__ logits,
                                                 const int* __restrict__ tgt,
                                                 float* __restrict__ rowloss)
{
    int n = blockIdx.x;
    const float* row = logits + (size_t)n * VOCAB;
    float m = -1e30f, ssum = 0.f;
    for (int i = threadIdx.x; i < VOCAB; i += 256) {
        float v = row[i];
        if (v > m) { ssum *= __expf(m - v); m = v; }
        ssum += __expf(v - m);
    }
    #pragma unroll
    for (int o = 16; o; o >>= 1) {
        float m2 = __shfl_xor_sync(0xffffffffu, m, o);
        float s2 = __shfl_xor_sync(0xffffffffu, ssum, o);
        float M  = fmaxf(m, m2);
        ssum = ssum*__expf(m - M) + s2*__expf(m2 - M);
        m = M;
    }
    __shared__ float smm[8], sms[8];
    int wid = threadIdx.x >> 5;
    if ((threadIdx.x & 31) == 0) { smm[wid] = m; sms[wid] = ssum; }
    __syncthreads();
    if (threadIdx.x == 0) {
        float M = smm[0], S = sms[0];
        for (int i = 1; i < 8; i++) {
            float M2 = fmaxf(M, smm[i]);
            S = S*__expf(M - M2) + sms[i]*__expf(smm[i] - M2);
            M = M2;
        }
        float lse = M + logf(S);
        rowloss[n] = lse - row[tgt[n]];
    }
}

__global__ void finalize_k(const float* __restrict__ rowloss, float* __restrict__ out_loss)
{
    float s = 0.f;
    for (int i = threadIdx.x; i < NTOK; i += 256) s += rowloss[i];
    #pragma unroll
    for (int o = 16; o; o >>= 1) s += __shfl_xor_sync(0xffffffffu, s, o);
    __shared__ float sm[8];
    int wid = threadIdx.x >> 5;
    if ((threadIdx.x & 31) == 0) sm[wid] = s;
    __syncthreads();
    if (threadIdx.x == 0) {
        float t = 0.f;
        for (int i = 0; i < 8; i++) t += sm[i];
        *out_loss = t * (1.0f/NTOK);
    }
}

// ---------------- launch -----------------------------------------------------
extern "C" void kernel_launch(void* const* d_in, const int* in_sizes, int n_in,
                              void* d_out, int out_size)
{
    const int*   idx     = (const int*)  d_in[0];
    const int*   targets = (const int*)  d_in[1];
    const float* wte     = (const float*)d_in[2];
    const float* wpe     = (const float*)d_in[3];
    const float* ln1_w   = (const float*)d_in[4];
    const float* ln1_b   = (const float*)d_in[5];
    const float* attn_w  = (const float*)d_in[6];
    const float* attn_b  = (const float*)d_in[7];
    const float* proj_w  = (const float*)d_in[8];
    const float* proj_b  = (const float*)d_in[9];
    const float* ln2_w   = (const float*)d_in[10];
    const float* ln2_b   = (const float*)d_in[11];
    const float* fc_w    = (const float*)d_in[12];
    const float* fc_b    = (const float*)d_in[13];
    const float* fcp_w   = (const float*)d_in[14];
    const float* fcp_b   = (const float*)d_in[15];
    const float* lnf_w   = (const float*)d_in[16];
    const float* lnf_b   = (const float*)d_in[17];

    float *px, *ph, *pqkv, *patt, *pffn, *plogfb, *prl;
    cudaGetSymbolAddress((void**)&px,    g_x);
    cudaGetSymbolAddress((void**)&ph,    g_h);
    cudaGetSymbolAddress((void**)&pqkv,  g_qkv);
    cudaGetSymbolAddress((void**)&patt,  g_att);
    cudaGetSymbolAddress((void**)&pffn,  g_ffn);
    cudaGetSymbolAddress((void**)&plogfb,g_logits_fallback);
    cudaGetSymbolAddress((void**)&prl,   g_rowloss);

    static bool attr_done = false;
    if (!attr_done) {
        cudaFuncSetAttribute(gemm_tc<EPI_NONE>,  cudaFuncAttributeMaxDynamicSharedMemorySize, GT_SMEM);
        cudaFuncSetAttribute(gemm_tc<EPI_GELU>,  cudaFuncAttributeMaxDynamicSharedMemorySize, GT_SMEM);
        cudaFuncSetAttribute(gemm_tc<EPI_RESID>, cudaFuncAttributeMaxDynamicSharedMemorySize, GT_SMEM);
        cudaFuncSetAttribute(attn_k, cudaFuncAttributeMaxDynamicSharedMemorySize, A_SMEM_FLOATS*4);
        attr_done = true;
    }

    const long long LOGN = (long long)NTOK * VOCAB;
    float* logits_ptr;
    float* loss_ptr = nullptr;
    if ((long long)out_size >= LOGN) {
        logits_ptr = (float*)d_out;
        if ((long long)out_size > LOGN) loss_ptr = (float*)d_out + LOGN;
    } else {
        logits_ptr = plogfb;
        loss_ptr = (float*)d_out;
    }

    embed_k<<<NTOK, 256>>>(idx, wte, wpe, px);

    dim3 gq (3*DMODEL/128, NTOK/128);
    dim3 gp (DMODEL/128,   NTOK/128);
    dim3 gf (4*DMODEL/128, NTOK/128);
    dim3 gv ((VOCAB+127)/128, NTOK/128);
    dim3 ga (SEQ/AQT, BATCH*NHEAD);

    for (int l = 0; l < LAYERS; l++) {
        ln_k<<<NTOK, 256>>>(px, ln1_w + (size_t)l*DMODEL, ln1_b + (size_t)l*DMODEL, ph);
        gemm_tc<EPI_NONE><<<gq, 256, GT_SMEM>>>(ph, attn_w + (size_t)l*3*DMODEL*DMODEL,
                                       attn_b + (size_t)l*3*DMODEL, nullptr,
                                       pqkv, NTOK, 3*DMODEL, DMODEL);
        attn_k<<<ga, 128, A_SMEM_FLOATS*4>>>(pqkv, patt);
        gemm_tc<EPI_RESID><<<gp, 256, GT_SMEM>>>(patt, proj_w + (size_t)l*DMODEL*DMODEL,
                                        proj_b + (size_t)l*DMODEL, px,
                                        px, NTOK, DMODEL, DMODEL);
        ln_k<<<NTOK, 256>>>(px, ln2_w + (size_t)l*DMODEL, ln2_b + (size_t)l*DMODEL, ph);
        gemm_tc<EPI_GELU><<<gf, 256, GT_SMEM>>>(ph, fc_w + (size_t)l*4*DMODEL*DMODEL,
                                       fc_b + (size_t)l*4*DMODEL, nullptr,
                                       pffn, NTOK, 4*DMODEL, DMODEL);
        gemm_tc<EPI_RESID><<<gp, 256, GT_SMEM>>>(pffn, fcp_w + (size_t)l*DMODEL*4*DMODEL,
                                        fcp_b + (size_t)l*DMODEL, px,
                                        px, NTOK, DMODEL, 4*DMODEL);
    }

    ln_k<<<NTOK, 256>>>(px, lnf_w, lnf_b, ph);
    gemm_tc<EPI_NONE><<<gv, 256, GT_SMEM>>>(ph, wte, nullptr, nullptr,
                                   logits_ptr, NTOK, VOCAB, DMODEL);

    if (loss_ptr) {
        rowloss_k<<<NTOK, 256>>>(logits_ptr, targets, prl);
        finalize_k<<<1, 256>>>(prl, loss_ptr);
    }
}

// round 5
// speedup vs baseline: 4.2904x; 1.2599x over previous
#include <cuda_runtime.h>
#include <math.h>
#include <stdint.h>

// Problem constants
#define LAYERS 6
#define NHEAD  16
#define DMODEL 1024
#define HDIM   64
#define BATCH  2
#define SEQ    1024
#define NTOK   (BATCH*SEQ)     // 2048
#define VOCAB  50257

// ---------------- scratch ----------------------------------------------------
__device__ float g_x   [NTOK*DMODEL];
__device__ float g_h   [NTOK*DMODEL];
__device__ float g_qkv [NTOK*3*DMODEL];
__device__ float g_att [NTOK*DMODEL];
__device__ float g_ffn [NTOK*4*DMODEL];
__device__ float g_logits_fallback[(size_t)NTOK*VOCAB];
__device__ float g_rowloss[NTOK];

// ---------------- PTX helpers (sm_80-portable only) --------------------------
__device__ __forceinline__ uint32_t smem_to_u32(const void* p) {
    uint32_t a;
    asm("{ .reg .u64 t; cvta.to.shared.u64 t, %1; cvt.u32.u64 %0, t; }" : "=r"(a) : "l"(p));
    return a;
}
__device__ __forceinline__ void cp_async16(uint32_t dst, const void* src, int srcsize) {
    asm volatile("cp.async.cg.shared.global [%0], [%1], 16, %2;\n"
                 :: "r"(dst), "l"(src), "r"(srcsize) : "memory");
}
#define CP_COMMIT() asm volatile("cp.async.commit_group;" ::: "memory")

#define LDSM_X4(r, a) \
    asm volatile("ldmatrix.sync.aligned.m8n8.x4.shared.b16 {%0,%1,%2,%3}, [%4];" \
        : "=r"((r)[0]), "=r"((r)[1]), "=r"((r)[2]), "=r"((r)[3]) : "r"(a))

#define MMA_TF32(d, a, b) \
    asm volatile("mma.sync.aligned.m16n8k8.row.col.f32.tf32.tf32.f32 " \
        "{%0,%1,%2,%3}, {%4,%5,%6,%7}, {%8,%9}, {%0,%1,%2,%3};" \
        : "+f"((d)[0]), "+f"((d)[1]), "+f"((d)[2]), "+f"((d)[3]) \
        : "r"((a)[0]), "r"((a)[1]), "r"((a)[2]), "r"((a)[3]), "r"((b)[0]), "r"((b)[1]))

__device__ __forceinline__ uint32_t cvt_tf32(uint32_t x) {
    uint32_t y;
    asm("cvt.rna.tf32.f32 %0, %1;" : "=r"(y) : "f"(__uint_as_float(x)));
    return y;
}
__device__ __forceinline__ float tf32r(float x) {
    uint32_t y;
    asm("cvt.rna.tf32.f32 %0, %1;" : "=r"(y) : "f"(x));
    return __uint_as_float(y);
}

// MUFU-free exp (B300 MUFU is ~0.5 op/cyc/SM): magic-number 2^n split + deg-5 poly.
__device__ __forceinline__ float fast_exp(float x) {
    x = fmaxf(x, -87.0f);
    float f = fminf(x * 1.44269504088896341f, 126.0f);
    float t = f + 12582912.0f;                 // 2^23 + 2^22
    int bits = __float_as_int(t);
    int n = (bits & 0x007FFFFF) - 0x00400000;
    float r = f - (t - 12582912.0f);           // r in [-0.5, 0.5]
    float p = 1.33335581e-3f;
    p = p * r + 9.61812911e-3f;
    p = p * r + 5.55041087e-2f;
    p = p * r + 2.40226507e-1f;
    p = p * r + 6.93147181e-1f;
    p = p * r + 1.0f;
    return p * __int_as_float((n + 127) << 23);
}

// ---------------- tf32 mma.sync NT GEMM: C[M,N] = A[M,K]*B[N,K]^T (+epi) -----
enum { EPI_NONE = 0, EPI_GELU = 1, EPI_RESID = 2 };

#define GBM 128
#define GBK 32
#define GSTAGES 3
#define GSTAGE_BYTES (GBM*GBK*4)                 // 16384
#define GT_SMEM (1024 + 2*GSTAGES*GSTAGE_BYTES)  // 99328

__device__ __forceinline__ uint32_t sw_off(int r, int c) {
    return (uint32_t)(r * 128 + ((c ^ (r & 7)) << 4));
}

template<int EPI>
__global__ void __launch_bounds__(256, 2) gemm_tc(
    const float* __restrict__ A, const float* __restrict__ B,
    const float* __restrict__ bias, const float* __restrict__ Rres,
    float* __restrict__ C, int M, int N, int K)
{
    extern __shared__ char dsm[];
    const int tid  = threadIdx.x;
    const int wid  = tid >> 5;
    const int lane = tid & 31;
    const int wm = wid >> 2;
    const int wn = wid & 3;
    const int bm = blockIdx.y * 128;
    const int bn = blockIdx.x * 128;

    uint32_t sbase = (smem_to_u32(dsm) + 1023u) & ~1023u;
    uint32_t aStage0 = sbase;
    uint32_t bStage0 = sbase + GSTAGES * GSTAGE_BYTES;

    const int T = K / GBK;

    auto load_tile = [&](int kt, int slot) {
        int k0 = kt * GBK;
        uint32_t aB = aStage0 + slot * GSTAGE_BYTES;
        uint32_t bB = bStage0 + slot * GSTAGE_BYTES;
        #pragma unroll
        for (int u = 0; u < 4; u++) {
            int f = tid + u * 256;
            int r = f >> 3, c = f & 7;
            cp_async16(aB + sw_off(r, c), A + (size_t)(bm + r) * K + k0 + c * 4, 16);
            int gb = bn + r;
            const float* bsrc = B + (size_t)(gb < N ? gb : 0) * K + k0 + c * 4;
            cp_async16(bB + sw_off(r, c), bsrc, gb < N ? 16 : 0);
        }
        CP_COMMIT();
    };

    float acc[4][4][4];
    #pragma unroll
    for (int i = 0; i < 4; i++)
        #pragma unroll
        for (int j = 0; j < 4; j++)
            #pragma unroll
            for (int v = 0; v < 4; v++) acc[i][j][v] = 0.f;

    load_tile(0, 0);
    load_tile(1, 1);
    load_tile(2, 2);

    for (int kt = 0; kt < T; kt++) {
        if (kt < T - 2)       asm volatile("cp.async.wait_group 2;" ::: "memory");
        else if (kt == T - 2) asm volatile("cp.async.wait_group 1;" ::: "memory");
        else                  asm volatile("cp.async.wait_group 0;" ::: "memory");
        __syncthreads();

        int slot = kt % GSTAGES;
        uint32_t aS = aStage0 + slot * GSTAGE_BYTES;
        uint32_t bS = bStage0 + slot * GSTAGE_BYTES;

        #pragma unroll
        for (int kk = 0; kk < 4; kk++) {
            uint32_t af[4][4];
            uint32_t bf[4][2];
            #pragma unroll
            for (int mb = 0; mb < 4; mb++) {
                int row = wm * 64 + mb * 16 + (lane & 15);
                int chunk = kk * 2 + (lane >> 4);
                LDSM_X4(af[mb], aS + row * 128 + ((chunk ^ (row & 7)) << 4));
            }
            #pragma unroll
            for (int p = 0; p < 2; p++) {
                uint32_t r4[4];
                int n = wn * 32 + p * 16 + (lane & 7) + ((lane >> 4) << 3);
                int chunk = kk * 2 + ((lane >> 3) & 1);
                LDSM_X4(r4, bS + n * 128 + ((chunk ^ (n & 7)) << 4));
                bf[p*2  ][0] = r4[0]; bf[p*2  ][1] = r4[1];
                bf[p*2+1][0] = r4[2]; bf[p*2+1][1] = r4[3];
            }
            #pragma unroll
            for (int mb = 0; mb < 4; mb++)
                #pragma unroll
                for (int v = 0; v < 4; v++) af[mb][v] = cvt_tf32(af[mb][v]);
            #pragma unroll
            for (int nb = 0; nb < 4; nb++) {
                bf[nb][0] = cvt_tf32(bf[nb][0]);
                bf[nb][1] = cvt_tf32(bf[nb][1]);
            }
            #pragma unroll
            for (int mb = 0; mb < 4; mb++)
                #pragma unroll
                for (int nb = 0; nb < 4; nb++)
                    MMA_TF32(acc[mb][nb], af[mb], bf[nb]);
        }
        __syncthreads();
        if (kt + GSTAGES < T) load_tile(kt + GSTAGES, slot);
    }

    // epilogue (alignment-safe: N may be odd, e.g. VOCAB=50257)
    #pragma unroll
    for (int mb = 0; mb < 4; mb++) {
        int r0 = bm + wm * 64 + mb * 16 + (lane >> 2);
        #pragma unroll
        for (int nb = 0; nb < 4; nb++) {
            int col = bn + wn * 32 + nb * 8 + (lane & 3) * 2;
            #pragma unroll
            for (int half = 0; half < 2; half++) {
                size_t row = (size_t)(r0 + half * 8);
                float v0 = acc[mb][nb][half*2 + 0];
                float v1 = acc[mb][nb][half*2 + 1];
                size_t base = row * (size_t)N + col;
                if (col + 1 < N) {
                    if (bias) { v0 += bias[col]; v1 += bias[col+1]; }
                    if (EPI == EPI_GELU) {
                        v0 = 0.5f*v0*(1.0f + erff(v0*0.70710678118654752f));
                        v1 = 0.5f*v1*(1.0f + erff(v1*0.70710678118654752f));
                    }
                    if (EPI == EPI_RESID) {
                        if ((base & 1) == 0) {
                            float2 rr = *(const float2*)(Rres + base);
                            v0 += rr.x; v1 += rr.y;
                        } else {
                            v0 += Rres[base]; v1 += Rres[base + 1];
                        }
                    }
                    if ((base & 1) == 0) {
                        *(float2*)(C + base) = make_float2(v0, v1);
                    } else {
                        C[base] = v0; C[base + 1] = v1;
                    }
                } else if (col < N) {
                    if (bias) v0 += bias[col];
                    if (EPI == EPI_GELU) v0 = 0.5f*v0*(1.0f + erff(v0*0.70710678118654752f));
                    if (EPI == EPI_RESID) v0 += Rres[base];
                    C[base] = v0;
                }
            }
        }
    }
}

// ---------------- embedding --------------------------------------------------
__global__ void embed_k(const int* __restrict__ idx,
                        const float* __restrict__ wte,
                        const float* __restrict__ wpe,
                        float* __restrict__ x)
{
    int n = blockIdx.x;
    int tok = idx[n];
    int t = n % SEQ;
    const float4* a = (const float4*)(wte + (size_t)tok * DMODEL);
    const float4* p = (const float4*)(wpe + (size_t)t   * DMODEL);
    float4* o = (float4*)(x + (size_t)n * DMODEL);
    for (int i = threadIdx.x; i < DMODEL/4; i += blockDim.x) {
        float4 u = a[i], v = p[i];
        o[i] = make_float4(u.x+v.x, u.y+v.y, u.z+v.z, u.w+v.w);
    }
}

// ---------------- layernorm --------------------------------------------------
__global__ void __launch_bounds__(256) ln_k(const float* __restrict__ x,
                                            const float* __restrict__ w,
                                            const float* __restrict__ b,
                                            float* __restrict__ out)
{
    int n = blockIdx.x;
    const float* row = x + (size_t)n * DMODEL;
    float s = 0.f, ss = 0.f;
    for (int i = threadIdx.x; i < DMODEL/4; i += 256) {
        float4 v = ((const float4*)row)[i];
        s  += v.x + v.y + v.z + v.w;
        ss += v.x*v.x + v.y*v.y + v.z*v.z + v.w*v.w;
    }
    #pragma unroll
    for (int o = 16; o; o >>= 1) {
        s  += __shfl_xor_sync(0xffffffffu, s,  o);
        ss += __shfl_xor_sync(0xffffffffu, ss, o);
    }
    __shared__ float sm[8], sm2[8];
    int wid = threadIdx.x >> 5;
    if ((threadIdx.x & 31) == 0) { sm[wid] = s; sm2[wid] = ss; }
    __syncthreads();
    if (threadIdx.x < 32) {
        s  = (threadIdx.x < 8) ? sm [threadIdx.x] : 0.f;
        ss = (threadIdx.x < 8) ? sm2[threadIdx.x] : 0.f;
        #pragma unroll
        for (int o = 4; o; o >>= 1) {
            s  += __shfl_xor_sync(0xffffffffu, s,  o);
            ss += __shfl_xor_sync(0xffffffffu, ss, o);
        }
        if (threadIdx.x == 0) { sm[0] = s; sm2[0] = ss; }
    }
    __syncthreads();
    float mean = sm[0] * (1.0f/DMODEL);
    float var  = sm2[0] * (1.0f/DMODEL) - mean*mean;
    float inv  = rsqrtf(var + 1e-5f);
    float* orow = out + (size_t)n * DMODEL;
    for (int i = threadIdx.x; i < DMODEL/4; i += 256) {
        float4 v  = ((const float4*)row)[i];
        float4 gw = ((const float4*)w)[i];
        float4 gb = ((const float4*)b)[i];
        float4 r;
        r.x = (v.x - mean)*inv*gw.x + gb.x;
        r.y = (v.y - mean)*inv*gw.y + gb.y;
        r.z = (v.z - mean)*inv*gw.z + gb.z;
        r.w = (v.w - mean)*inv*gw.w + gb.w;
        ((float4*)orow)[i] = r;
    }
}

// ---------------- tensor-core flash attention --------------------------------
// 256 threads (8 warps), Q tile 128, K tile 64. tf32 mma for QK^T and P@V.
// smem bytes: Qs 32768 | Ks 16384 | VT 16384 | Ps 128*68*4=34816 => 100352
#define AT_KT 64
#define AT_SMEM 100352
#define PS_STRIDE 68

__device__ __forceinline__ uint32_t att_off(int r, int c /*16B chunk 0..15*/) {
    return (uint32_t)(r * 256 + ((c & 8) << 4) + (((c & 7) ^ (r & 7)) << 4));
}

__global__ void __launch_bounds__(256) attn_k(const float* __restrict__ qkv,
                                              float* __restrict__ y)
{
    extern __shared__ float smf[];
    uint32_t qsB = smem_to_u32(smf);
    uint32_t ksB = qsB + 32768;
    uint32_t vtB = qsB + 49152;
    float* Ps = smf + 16384;

    const int bh = blockIdx.y;
    const int b = bh >> 4, h = bh & 15;
    const int q0 = blockIdx.x * 128;
    const int tid = threadIdx.x, wid = tid >> 5, lane = tid & 31;
    const int wq = wid * 16;
    const int qtr = lane >> 2;
    const int qlc = lane & 3;

    // load Q tile (scaled by 1/8, tf32-rounded), swizzled
    #pragma unroll
    for (int u = 0; u < 8; u++) {
        int f = tid + u * 256;
        int r = f >> 4, c = f & 15;
        float4 v = *(const float4*)(qkv + (size_t)(b*SEQ + q0 + r)*3*DMODEL + h*HDIM + c*4);
        float4 w;
        w.x = tf32r(v.x * 0.125f); w.y = tf32r(v.y * 0.125f);
        w.z = tf32r(v.z * 0.125f); w.w = tf32r(v.w * 0.125f);
        *(float4*)((char*)smf + att_off(r, c)) = w;
    }

    float m0 = -1e30f, m1 = -1e30f, l0 = 0.f, l1 = 0.f;
    float o[8][4];
    #pragma unroll
    for (int nb = 0; nb < 8; nb++)
        #pragma unroll
        for (int v = 0; v < 4; v++) o[nb][v] = 0.f;

    const int row0 = q0 + wq + qtr;

    for (int k0 = 0; k0 < q0 + 128; k0 += AT_KT) {
        __syncthreads();
        // K tile (tf32-rounded, swizzled)
        #pragma unroll
        for (int u = 0; u < 4; u++) {
            int f = tid + u * 256;
            int r = f >> 4, c = f & 15;
            float4 v = *(const float4*)(qkv + (size_t)(b*SEQ + k0 + r)*3*DMODEL + DMODEL + h*HDIM + c*4);
            float4 w;
            w.x = tf32r(v.x); w.y = tf32r(v.y); w.z = tf32r(v.z); w.w = tf32r(v.w);
            *(float4*)((char*)smf + 32768 + att_off(r, c)) = w;
        }
        // V^T tile (transpose scatter, tf32-rounded)
        #pragma unroll
        for (int u = 0; u < 4; u++) {
            int f = tid + u * 256;
            int kt = f >> 4, c = f & 15;
            float4 v = *(const float4*)(qkv + (size_t)(b*SEQ + k0 + kt)*3*DMODEL + 2*DMODEL + h*HDIM + c*4);
            float vv[4] = {v.x, v.y, v.z, v.w};
            #pragma unroll
            for (int j = 0; j < 4; j++) {
                int d = c * 4 + j;
                *(float*)((char*)smf + 49152 + att_off(d, kt >> 2) + (kt & 3) * 4) = tf32r(vv[j]);
            }
        }
        __syncthreads();

        // ---- QK^T ----
        float sc[8][4];
        #pragma unroll
        for (int nb = 0; nb < 8; nb++)
            #pragma unroll
            for (int v = 0; v < 4; v++) sc[nb][v] = 0.f;

        #pragma unroll
        for (int ks8 = 0; ks8 < 8; ks8++) {
            uint32_t af[4];
            LDSM_X4(af, qsB + att_off(wq + (lane & 15), 2*ks8 + (lane >> 4)));
            #pragma unroll
            for (int g = 0; g < 4; g++) {
                uint32_t r4[4];
                int n = g * 16 + (lane & 7) + ((lane >> 4) << 3);
                int ch = 2*ks8 + ((lane >> 3) & 1);
                LDSM_X4(r4, ksB + att_off(n, ch));
                uint32_t b0[2] = {r4[0], r4[1]};
                uint32_t b1[2] = {r4[2], r4[3]};
                MMA_TF32(sc[g*2    ], af, b0);
                MMA_TF32(sc[g*2 + 1], af, b1);
            }
        }

        // ---- causal mask ----
        if (k0 + AT_KT - 1 > q0 + wq) {
            #pragma unroll
            for (int nb = 0; nb < 8; nb++) {
                int c0 = k0 + nb*8 + qlc*2;
                if (c0     > row0    ) sc[nb][0] = -1e30f;
                if (c0 + 1 > row0    ) sc[nb][1] = -1e30f;
                if (c0     > row0 + 8) sc[nb][2] = -1e30f;
                if (c0 + 1 > row0 + 8) sc[nb][3] = -1e30f;
            }
        }

        // ---- online softmax ----
        float mx0 = sc[0][0], mx1 = sc[0][2];
        #pragma unroll
        for (int nb = 0; nb < 8; nb++) {
            mx0 = fmaxf(mx0, fmaxf(sc[nb][0], sc[nb][1]));
            mx1 = fmaxf(mx1, fmaxf(sc[nb][2], sc[nb][3]));
        }
        mx0 = fmaxf(mx0, __shfl_xor_sync(0xffffffffu, mx0, 1));
        mx0 = fmaxf(mx0, __shfl_xor_sync(0xffffffffu, mx0, 2));
        mx1 = fmaxf(mx1, __shfl_xor_sync(0xffffffffu, mx1, 1));
        mx1 = fmaxf(mx1, __shfl_xor_sync(0xffffffffu, mx1, 2));
        float nm0 = fmaxf(m0, mx0), nm1 = fmaxf(m1, mx1);
        float corr0 = fast_exp(m0 - nm0), corr1 = fast_exp(m1 - nm1);
        float s0 = 0.f, s1 = 0.f;
        #pragma unroll
        for (int nb = 0; nb < 8; nb++) {
            sc[nb][0] = fast_exp(sc[nb][0] - nm0);
            sc[nb][1] = fast_exp(sc[nb][1] - nm0);
            sc[nb][2] = fast_exp(sc[nb][2] - nm1);
            sc[nb][3] = fast_exp(sc[nb][3] - nm1);
            s0 += sc[nb][0] + sc[nb][1];
            s1 += sc[nb][2] + sc[nb][3];
        }
        s0 += __shfl_xor_sync(0xffffffffu, s0, 1);
        s0 += __shfl_xor_sync(0xffffffffu, s0, 2);
        s1 += __shfl_xor_sync(0xffffffffu, s1, 1);
        s1 += __shfl_xor_sync(0xffffffffu, s1, 2);
        l0 = l0 * corr0 + s0;  m0 = nm0;
        l1 = l1 * corr1 + s1;  m1 = nm1;
        #pragma unroll
        for (int nb = 0; nb < 8; nb++) {
            o[nb][0] *= corr0; o[nb][1] *= corr0;
            o[nb][2] *= corr1; o[nb][3] *= corr1;
        }

        // ---- P frags -> smem (tf32-rounded), warp-local ----
        int pr = wq + qtr;
        #pragma unroll
        for (int nb = 0; nb < 8; nb++) {
            int pc = nb*8 + qlc*2;
            Ps[pr*PS_STRIDE + pc    ] = tf32r(sc[nb][0]);
            Ps[pr*PS_STRIDE + pc + 1] = tf32r(sc[nb][1]);
            Ps[(pr+8)*PS_STRIDE + pc    ] = tf32r(sc[nb][2]);
            Ps[(pr+8)*PS_STRIDE + pc + 1] = tf32r(sc[nb][3]);
        }
        __syncwarp();

        // ---- P @ V ----
        #pragma unroll
        for (int ks8 = 0; ks8 < 8; ks8++) {
            uint32_t pa[4];
            int pk = ks8*8 + qlc;
            pa[0] = __float_as_uint(Ps[(wq + qtr    )*PS_STRIDE + pk    ]);
            pa[1] = __float_as_uint(Ps[(wq + qtr + 8)*PS_STRIDE + pk    ]);
            pa[2] = __float_as_uint(Ps[(wq + qtr    )*PS_STRIDE + pk + 4]);
            pa[3] = __float_as_uint(Ps[(wq + qtr + 8)*PS_STRIDE + pk + 4]);
            #pragma unroll
            for (int g = 0; g < 4; g++) {
                uint32_t r4[4];
                int n = g * 16 + (lane & 7) + ((lane >> 4) << 3);
                int ch = 2*ks8 + ((lane >> 3) & 1);
                LDSM_X4(r4, vtB + att_off(n, ch));
                uint32_t b0[2] = {r4[0], r4[1]};
                uint32_t b1[2] = {r4[2], r4[3]};
                MMA_TF32(o[g*2    ], pa, b0);
                MMA_TF32(o[g*2 + 1], pa, b1);
            }
        }
        __syncwarp();
    }

    float inv0 = 1.0f / l0, inv1 = 1.0f / l1;
    size_t g0 = (size_t)(b*SEQ + q0 + wq + qtr) * DMODEL + h*HDIM;
    size_t g1 = g0 + 8 * DMODEL;
    #pragma unroll
    for (int nb = 0; nb < 8; nb++) {
        int d0 = nb*8 + qlc*2;
        *(float2*)(y + g0 + d0) = make_float2(o[nb][0]*inv0, o[nb][1]*inv0);
        *(float2*)(y + g1 + d0) = make_float2(o[nb][2]*inv1, o[nb][3]*inv1);
    }
}

// ---------------- loss -------------------------------------------------------
__global__ void __launch_bounds__(256) rowloss_k(const float* __restrict__ logits,
                                                 const int* __restrict__ tgt,
                                                 float* __restrict__ rowloss)
{
    int n = blockIdx.x;
    const float* row = logits + (size_t)n * VOCAB;
    float m = -1e30f, ssum = 0.f;
    for (int i = threadIdx.x; i < VOCAB; i += 256) {
        float v = row[i];
        if (v > m) { ssum *= fast_exp(m - v); m = v; }
        ssum += fast_exp(v - m);
    }
    #pragma unroll
    for (int o = 16; o; o >>= 1) {
        float m2 = __shfl_xor_sync(0xffffffffu, m, o);
        float s2 = __shfl_xor_sync(0xffffffffu, ssum, o);
        float M  = fmaxf(m, m2);
        ssum = ssum*fast_exp(m - M) + s2*fast_exp(m2 - M);
        m = M;
    }
    __shared__ float smm[8], sms[8];
    int wid = threadIdx.x >> 5;
    if ((threadIdx.x & 31) == 0) { smm[wid] = m; sms[wid] = ssum; }
    __syncthreads();
    if (threadIdx.x == 0) {
        float M = smm[0], S = sms[0];
        for (int i = 1; i < 8; i++) {
            float M2 = fmaxf(M, smm[i]);
            S = S*fast_exp(M - M2) + sms[i]*fast_exp(smm[i] - M2);
            M = M2;
        }
        float lse = M + logf(S);
        rowloss[n] = lse - row[tgt[n]];
    }
}

__global__ void finalize_k(const float* __restrict__ rowloss, float* __restrict__ out_loss)
{
    float s = 0.f;
    for (int i = threadIdx.x; i < NTOK; i += 256) s += rowloss[i];
    #pragma unroll
    for (int o = 16; o; o >>= 1) s += __shfl_xor_sync(0xffffffffu, s, o);
    __shared__ float sm[8];
    int wid = threadIdx.x >> 5;
    if ((threadIdx.x & 31) == 0) sm[wid] = s;
    __syncthreads();
    if (threadIdx.x == 0) {
        float t = 0.f;
        for (int i = 0; i < 8; i++) t += sm[i];
        *out_loss = t * (1.0f/NTOK);
    }
}

// ---------------- launch -----------------------------------------------------
extern "C" void kernel_launch(void* const* d_in, const int* in_sizes, int n_in,
                              void* d_out, int out_size)
{
    const int*   idx     = (const int*)  d_in[0];
    const int*   targets = (const int*)  d_in[1];
    const float* wte     = (const float*)d_in[2];
    const float* wpe     = (const float*)d_in[3];
    const float* ln1_w   = (const float*)d_in[4];
    const float* ln1_b   = (const float*)d_in[5];
    const float* attn_w  = (const float*)d_in[6];
    const float* attn_b  = (const float*)d_in[7];
    const float* proj_w  = (const float*)d_in[8];
    const float* proj_b  = (const float*)d_in[9];
    const float* ln2_w   = (const float*)d_in[10];
    const float* ln2_b   = (const float*)d_in[11];
    const float* fc_w    = (const float*)d_in[12];
    const float* fc_b    = (const float*)d_in[13];
    const float* fcp_w   = (const float*)d_in[14];
    const float* fcp_b   = (const float*)d_in[15];
    const float* lnf_w   = (const float*)d_in[16];
    const float* lnf_b   = (const float*)d_in[17];

    float *px, *ph, *pqkv, *patt, *pffn, *plogfb, *prl;
    cudaGetSymbolAddress((void**)&px,    g_x);
    cudaGetSymbolAddress((void**)&ph,    g_h);
    cudaGetSymbolAddress((void**)&pqkv,  g_qkv);
    cudaGetSymbolAddress((void**)&patt,  g_att);
    cudaGetSymbolAddress((void**)&pffn,  g_ffn);
    cudaGetSymbolAddress((void**)&plogfb,g_logits_fallback);
    cudaGetSymbolAddress((void**)&prl,   g_rowloss);

    static bool attr_done = false;
    if (!attr_done) {
        cudaFuncSetAttribute(gemm_tc<EPI_NONE>,  cudaFuncAttributeMaxDynamicSharedMemorySize, GT_SMEM);
        cudaFuncSetAttribute(gemm_tc<EPI_GELU>,  cudaFuncAttributeMaxDynamicSharedMemorySize, GT_SMEM);
        cudaFuncSetAttribute(gemm_tc<EPI_RESID>, cudaFuncAttributeMaxDynamicSharedMemorySize, GT_SMEM);
        cudaFuncSetAttribute(attn_k, cudaFuncAttributeMaxDynamicSharedMemorySize, AT_SMEM);
        attr_done = true;
    }

    const long long LOGN = (long long)NTOK * VOCAB;
    float* logits_ptr;
    float* loss_ptr = nullptr;
    if ((long long)out_size >= LOGN) {
        logits_ptr = (float*)d_out;
        if ((long long)out_size > LOGN) loss_ptr = (float*)d_out + LOGN;
    } else {
        logits_ptr = plogfb;
        loss_ptr = (float*)d_out;
    }

    embed_k<<<NTOK, 256>>>(idx, wte, wpe, px);

    dim3 gq (3*DMODEL/128, NTOK/128);
    dim3 gp (DMODEL/128,   NTOK/128);
    dim3 gf (4*DMODEL/128, NTOK/128);
    dim3 gv ((VOCAB+127)/128, NTOK/128);
    dim3 ga (SEQ/128, BATCH*NHEAD);

    for (int l = 0; l < LAYERS; l++) {
        ln_k<<<NTOK, 256>>>(px, ln1_w + (size_t)l*DMODEL, ln1_b + (size_t)l*DMODEL, ph);
        gemm_tc<EPI_NONE><<<gq, 256, GT_SMEM>>>(ph, attn_w + (size_t)l*3*DMODEL*DMODEL,
                                       attn_b + (size_t)l*3*DMODEL, nullptr,
                                       pqkv, NTOK, 3*DMODEL, DMODEL);
        attn_k<<<ga, 256, AT_SMEM>>>(pqkv, patt);
        gemm_tc<EPI_RESID><<<gp, 256, GT_SMEM>>>(patt, proj_w + (size_t)l*DMODEL*DMODEL,
                                        proj_b + (size_t)l*DMODEL, px,
                                        px, NTOK, DMODEL, DMODEL);
        ln_k<<<NTOK, 256>>>(px, ln2_w + (size_t)l*DMODEL, ln2_b + (size_t)l*DMODEL, ph);
        gemm_tc<EPI_GELU><<<gf, 256, GT_SMEM>>>(ph, fc_w + (size_t)l*4*DMODEL*DMODEL,
                                       fc_b + (size_t)l*4*DMODEL, nullptr,
                                       pffn, NTOK, 4*DMODEL, DMODEL);
        gemm_tc<EPI_RESID><<<gp, 256, GT_SMEM>>>(pffn, fcp_w + (size_t)l*DMODEL*4*DMODEL,
                                        fcp_b + (size_t)l*DMODEL, px,
                                        px, NTOK, DMODEL, 4*DMODEL);
    }

    ln_k<<<NTOK, 256>>>(px, lnf_w, lnf_b, ph);
    gemm_tc<EPI_NONE><<<gv, 256, GT_SMEM>>>(ph, wte, nullptr, nullptr,
                                   logits_ptr, NTOK, VOCAB, DMODEL);

    if (loss_ptr) {
        rowloss_k<<<NTOK, 256>>>(logits_ptr, targets, prl);
        finalize_k<<<1, 256>>>(prl, loss_ptr);
    }
}

// round 6
// speedup vs baseline: 4.6473x; 1.0832x over previous
#include <cuda_runtime.h>
#include <math.h>
#include <stdint.h>

// Problem constants
#define LAYERS 6
#define NHEAD  16
#define DMODEL 1024
#define HDIM   64
#define BATCH  2
#define SEQ    1024
#define NTOK   (BATCH*SEQ)     // 2048
#define VOCAB  50257
#define NVTILE ((VOCAB+127)/128)     // 393
#define PCOLS  (NVTILE*4)            // 1572 loss partials per row

// ---------------- scratch ----------------------------------------------------
__device__ float g_x   [NTOK*DMODEL];
__device__ float g_h   [NTOK*DMODEL];
__device__ float g_qkv [NTOK*3*DMODEL];
__device__ float g_att [NTOK*DMODEL];
__device__ float g_ffn [NTOK*4*DMODEL];
__device__ float g_logits_fallback[(size_t)NTOK*VOCAB];
__device__ float g_rowloss[NTOK];
__device__ float g_pm[(size_t)NTOK*PCOLS];
__device__ float g_ps[(size_t)NTOK*PCOLS];

// ---------------- PTX helpers (sm_80-portable only) --------------------------
__device__ __forceinline__ uint32_t smem_to_u32(const void* p) {
    uint32_t a;
    asm("{ .reg .u64 t; cvta.to.shared.u64 t, %1; cvt.u32.u64 %0, t; }" : "=r"(a) : "l"(p));
    return a;
}
__device__ __forceinline__ void cp_async16(uint32_t dst, const void* src, int srcsize) {
    asm volatile("cp.async.cg.shared.global [%0], [%1], 16, %2;\n"
                 :: "r"(dst), "l"(src), "r"(srcsize) : "memory");
}
#define CP_COMMIT() asm volatile("cp.async.commit_group;" ::: "memory")

#define LDSM_X4(r, a) \
    asm volatile("ldmatrix.sync.aligned.m8n8.x4.shared.b16 {%0,%1,%2,%3}, [%4];" \
        : "=r"((r)[0]), "=r"((r)[1]), "=r"((r)[2]), "=r"((r)[3]) : "r"(a))

#define MMA_TF32(d, a, b) \
    asm volatile("mma.sync.aligned.m16n8k8.row.col.f32.tf32.tf32.f32 " \
        "{%0,%1,%2,%3}, {%4,%5,%6,%7}, {%8,%9}, {%0,%1,%2,%3};" \
        : "+f"((d)[0]), "+f"((d)[1]), "+f"((d)[2]), "+f"((d)[3]) \
        : "r"((a)[0]), "r"((a)[1]), "r"((a)[2]), "r"((a)[3]), "r"((b)[0]), "r"((b)[1]))

__device__ __forceinline__ uint32_t cvt_tf32(uint32_t x) {
    uint32_t y;
    asm("cvt.rna.tf32.f32 %0, %1;" : "=r"(y) : "f"(__uint_as_float(x)));
    return y;
}
__device__ __forceinline__ float tf32r(float x) {
    uint32_t y;
    asm("cvt.rna.tf32.f32 %0, %1;" : "=r"(y) : "f"(x));
    return __uint_as_float(y);
}

// MUFU-free exp (B300 MUFU is ~0.5 op/cyc/SM): magic-number 2^n split + deg-5 poly.
__device__ __forceinline__ float fast_exp(float x) {
    x = fmaxf(x, -87.0f);
    float f = fminf(x * 1.44269504088896341f, 126.0f);
    float t = f + 12582912.0f;                 // 2^23 + 2^22
    int bits = __float_as_int(t);
    int n = (bits & 0x007FFFFF) - 0x00400000;
    float r = f - (t - 12582912.0f);           // r in [-0.5, 0.5]
    float p = 1.33335581e-3f;
    p = p * r + 9.61812911e-3f;
    p = p * r + 5.55041087e-2f;
    p = p * r + 2.40226507e-1f;
    p = p * r + 6.93147181e-1f;
    p = p * r + 1.0f;
    return p * __int_as_float((n + 127) << 23);
}

// ---------------- tf32 mma.sync NT GEMM: C[M,N] = A[M,K]*B[N,K]^T (+epi) -----
// A operands are produced tf32-pre-rounded by our own kernels -> no A cvts.
enum { EPI_NONE = 0, EPI_GELU = 1, EPI_RESID = 2, EPI_LOSS = 3 };

#define GBM 128
#define GBK 32
#define GSTAGES 3
#define GSTAGE_BYTES (GBM*GBK*4)                 // 16384
#define GT_SMEM (1024 + 2*GSTAGES*GSTAGE_BYTES)  // 99328

__device__ __forceinline__ uint32_t sw_off(int r, int c) {
    return (uint32_t)(r * 128 + ((c ^ (r & 7)) << 4));
}

template<int EPI>
__global__ void __launch_bounds__(256, 2) gemm_tc(
    const float* __restrict__ A, const float* __restrict__ B,
    const float* __restrict__ bias, const float* __restrict__ Rres,
    float* __restrict__ C, int M, int N, int K,
    float* __restrict__ Pm, float* __restrict__ Psum)
{
    extern __shared__ char dsm[];
    const int tid  = threadIdx.x;
    const int wid  = tid >> 5;
    const int lane = tid & 31;
    const int wm = wid >> 2;
    const int wn = wid & 3;
    const int bm = blockIdx.y * 128;
    const int bn = blockIdx.x * 128;

    uint32_t sbase = (smem_to_u32(dsm) + 1023u) & ~1023u;
    uint32_t aStage0 = sbase;
    uint32_t bStage0 = sbase + GSTAGES * GSTAGE_BYTES;

    const int T = K / GBK;

    auto load_tile = [&](int kt, int slot) {
        int k0 = kt * GBK;
        uint32_t aB = aStage0 + slot * GSTAGE_BYTES;
        uint32_t bB = bStage0 + slot * GSTAGE_BYTES;
        #pragma unroll
        for (int u = 0; u < 4; u++) {
            int f = tid + u * 256;
            int r = f >> 3, c = f & 7;
            cp_async16(aB + sw_off(r, c), A + (size_t)(bm + r) * K + k0 + c * 4, 16);
            int gb = bn + r;
            const float* bsrc = B + (size_t)(gb < N ? gb : 0) * K + k0 + c * 4;
            cp_async16(bB + sw_off(r, c), bsrc, gb < N ? 16 : 0);
        }
        CP_COMMIT();
    };

    float acc[4][4][4];
    #pragma unroll
    for (int i = 0; i < 4; i++)
        #pragma unroll
        for (int j = 0; j < 4; j++)
            #pragma unroll
            for (int v = 0; v < 4; v++) acc[i][j][v] = 0.f;

    load_tile(0, 0);
    load_tile(1, 1);
    load_tile(2, 2);

    for (int kt = 0; kt < T; kt++) {
        if (kt < T - 2)       asm volatile("cp.async.wait_group 2;" ::: "memory");
        else if (kt == T - 2) asm volatile("cp.async.wait_group 1;" ::: "memory");
        else                  asm volatile("cp.async.wait_group 0;" ::: "memory");
        __syncthreads();

        int slot = kt % GSTAGES;
        uint32_t aS = aStage0 + slot * GSTAGE_BYTES;
        uint32_t bS = bStage0 + slot * GSTAGE_BYTES;

        #pragma unroll
        for (int kk = 0; kk < 4; kk++) {
            uint32_t af[4][4];
            uint32_t bf[4][2];
            #pragma unroll
            for (int mb = 0; mb < 4; mb++) {
                int row = wm * 64 + mb * 16 + (lane & 15);
                int chunk = kk * 2 + (lane >> 4);
                LDSM_X4(af[mb], aS + row * 128 + ((chunk ^ (row & 7)) << 4));
            }
            #pragma unroll
            for (int p = 0; p < 2; p++) {
                uint32_t r4[4];
                int n = wn * 32 + p * 16 + (lane & 7) + ((lane >> 4) << 3);
                int chunk = kk * 2 + ((lane >> 3) & 1);
                LDSM_X4(r4, bS + n * 128 + ((chunk ^ (n & 7)) << 4));
                bf[p*2  ][0] = r4[0]; bf[p*2  ][1] = r4[1];
                bf[p*2+1][0] = r4[2]; bf[p*2+1][1] = r4[3];
            }
            // A pre-rounded by producer; only B (raw weights) needs rounding.
            #pragma unroll
            for (int nb = 0; nb < 4; nb++) {
                bf[nb][0] = cvt_tf32(bf[nb][0]);
                bf[nb][1] = cvt_tf32(bf[nb][1]);
            }
            #pragma unroll
            for (int mb = 0; mb < 4; mb++)
                #pragma unroll
                for (int nb = 0; nb < 4; nb++)
                    MMA_TF32(acc[mb][nb], af[mb], bf[nb]);
        }
        __syncthreads();
        if (kt + GSTAGES < T) load_tile(kt + GSTAGES, slot);
    }

    if (EPI == EPI_LOSS) {
        // store logits + per-warp (max, sumexp) partials for the loss
        #pragma unroll
        for (int mb = 0; mb < 4; mb++) {
            #pragma unroll
            for (int half = 0; half < 2; half++) {
                int rrow = bm + wm * 64 + mb * 16 + (lane >> 2) + half * 8;
                float vals[8];
                float vmax = -1e30f;
                #pragma unroll
                for (int nb = 0; nb < 4; nb++) {
                    int col = bn + wn * 32 + nb * 8 + (lane & 3) * 2;
                    float v0 = acc[mb][nb][half*2 + 0];
                    float v1 = acc[mb][nb][half*2 + 1];
                    size_t base = (size_t)rrow * N + col;
                    if (col + 1 < N) {
                        if ((base & 1) == 0) *(float2*)(C + base) = make_float2(v0, v1);
                        else { C[base] = v0; C[base + 1] = v1; }
                    } else if (col < N) {
                        C[base] = v0;
                    }
                    vals[nb*2    ] = (col     < N) ? v0 : -1e30f;
                    vals[nb*2 + 1] = (col + 1 < N) ? v1 : -1e30f;
                    vmax = fmaxf(vmax, fmaxf(vals[nb*2], vals[nb*2+1]));
                }
                vmax = fmaxf(vmax, __shfl_xor_sync(0xffffffffu, vmax, 1));
                vmax = fmaxf(vmax, __shfl_xor_sync(0xffffffffu, vmax, 2));
                float s = 0.f;
                #pragma unroll
                for (int j = 0; j < 8; j++) s += fast_exp(vals[j] - vmax);
                s += __shfl_xor_sync(0xffffffffu, s, 1);
                s += __shfl_xor_sync(0xffffffffu, s, 2);
                if ((lane & 3) == 0) {
                    size_t po = (size_t)rrow * PCOLS + blockIdx.x * 4 + wn;
                    Pm[po] = vmax;
                    Psum[po] = s;
                }
            }
        }
        return;
    }

    // generic epilogue (alignment-safe: N may be odd)
    #pragma unroll
    for (int mb = 0; mb < 4; mb++) {
        int r0 = bm + wm * 64 + mb * 16 + (lane >> 2);
        #pragma unroll
        for (int nb = 0; nb < 4; nb++) {
            int col = bn + wn * 32 + nb * 8 + (lane & 3) * 2;
            #pragma unroll
            for (int half = 0; half < 2; half++) {
                size_t row = (size_t)(r0 + half * 8);
                float v0 = acc[mb][nb][half*2 + 0];
                float v1 = acc[mb][nb][half*2 + 1];
                size_t base = row * (size_t)N + col;
                if (col + 1 < N) {
                    if (bias) { v0 += bias[col]; v1 += bias[col+1]; }
                    if (EPI == EPI_GELU) {
                        v0 = tf32r(0.5f*v0*(1.0f + erff(v0*0.70710678118654752f)));
                        v1 = tf32r(0.5f*v1*(1.0f + erff(v1*0.70710678118654752f)));
                    }
                    if (EPI == EPI_RESID) {
                        if ((base & 1) == 0) {
                            float2 rr = *(const float2*)(Rres + base);
                            v0 += rr.x; v1 += rr.y;
                        } else {
                            v0 += Rres[base]; v1 += Rres[base + 1];
                        }
                    }
                    if ((base & 1) == 0) {
                        *(float2*)(C + base) = make_float2(v0, v1);
                    } else {
                        C[base] = v0; C[base + 1] = v1;
                    }
                } else if (col < N) {
                    if (bias) v0 += bias[col];
                    if (EPI == EPI_GELU) v0 = tf32r(0.5f*v0*(1.0f + erff(v0*0.70710678118654752f)));
                    if (EPI == EPI_RESID) v0 += Rres[base];
                    C[base] = v0;
                }
            }
        }
    }
}

// ---------------- embedding --------------------------------------------------
__global__ void embed_k(const int* __restrict__ idx,
                        const float* __restrict__ wte,
                        const float* __restrict__ wpe,
                        float* __restrict__ x)
{
    int n = blockIdx.x;
    int tok = idx[n];
    int t = n % SEQ;
    const float4* a = (const float4*)(wte + (size_t)tok * DMODEL);
    const float4* p = (const float4*)(wpe + (size_t)t   * DMODEL);
    float4* o = (float4*)(x + (size_t)n * DMODEL);
    for (int i = threadIdx.x; i < DMODEL/4; i += blockDim.x) {
        float4 u = a[i], v = p[i];
        o[i] = make_float4(u.x+v.x, u.y+v.y, u.z+v.z, u.w+v.w);
    }
}

// ---------------- layernorm (output tf32-pre-rounded: it only feeds GEMM A) --
__global__ void __launch_bounds__(256) ln_k(const float* __restrict__ x,
                                            const float* __restrict__ w,
                                            const float* __restrict__ b,
                                            float* __restrict__ out)
{
    int n = blockIdx.x;
    const float* row = x + (size_t)n * DMODEL;
    float s = 0.f, ss = 0.f;
    for (int i = threadIdx.x; i < DMODEL/4; i += 256) {
        float4 v = ((const float4*)row)[i];
        s  += v.x + v.y + v.z + v.w;
        ss += v.x*v.x + v.y*v.y + v.z*v.z + v.w*v.w;
    }
    #pragma unroll
    for (int o = 16; o; o >>= 1) {
        s  += __shfl_xor_sync(0xffffffffu, s,  o);
        ss += __shfl_xor_sync(0xffffffffu, ss, o);
    }
    __shared__ float sm[8], sm2[8];
    int wid = threadIdx.x >> 5;
    if ((threadIdx.x & 31) == 0) { sm[wid] = s; sm2[wid] = ss; }
    __syncthreads();
    if (threadIdx.x < 32) {
        s  = (threadIdx.x < 8) ? sm [threadIdx.x] : 0.f;
        ss = (threadIdx.x < 8) ? sm2[threadIdx.x] : 0.f;
        #pragma unroll
        for (int o = 4; o; o >>= 1) {
            s  += __shfl_xor_sync(0xffffffffu, s,  o);
            ss += __shfl_xor_sync(0xffffffffu, ss, o);
        }
        if (threadIdx.x == 0) { sm[0] = s; sm2[0] = ss; }
    }
    __syncthreads();
    float mean = sm[0] * (1.0f/DMODEL);
    float var  = sm2[0] * (1.0f/DMODEL) - mean*mean;
    float inv  = rsqrtf(var + 1e-5f);
    float* orow = out + (size_t)n * DMODEL;
    for (int i = threadIdx.x; i < DMODEL/4; i += 256) {
        float4 v  = ((const float4*)row)[i];
        float4 gw = ((const float4*)w)[i];
        float4 gb = ((const float4*)b)[i];
        float4 r;
        r.x = tf32r((v.x - mean)*inv*gw.x + gb.x);
        r.y = tf32r((v.y - mean)*inv*gw.y + gb.y);
        r.z = tf32r((v.z - mean)*inv*gw.z + gb.z);
        r.w = tf32r((v.w - mean)*inv*gw.w + gb.w);
        ((float4*)orow)[i] = r;
    }
}

// ---------------- tensor-core flash attention --------------------------------
// 256 threads (8 warps), Q tile 128, K tile 64. tf32 mma for QK^T and P@V.
// Heavy q-tiles scheduled first (LPT) via reversed blockIdx.x mapping.
#define AT_KT 64
#define AT_SMEM 100352
#define PS_STRIDE 68

__device__ __forceinline__ uint32_t att_off(int r, int c /*16B chunk 0..15*/) {
    return (uint32_t)(r * 256 + ((c & 8) << 4) + (((c & 7) ^ (r & 7)) << 4));
}

__global__ void __launch_bounds__(256) attn_k(const float* __restrict__ qkv,
                                              float* __restrict__ y)
{
    extern __shared__ float smf[];
    uint32_t qsB = smem_to_u32(smf);
    uint32_t ksB = qsB + 32768;
    uint32_t vtB = qsB + 49152;
    float* Ps = smf + 16384;

    const int bh = blockIdx.y;
    const int b = bh >> 4, h = bh & 15;
    const int q0 = (gridDim.x - 1 - blockIdx.x) * 128;   // heavy tiles first
    const int tid = threadIdx.x, wid = tid >> 5, lane = tid & 31;
    const int wq = wid * 16;
    const int qtr = lane >> 2;
    const int qlc = lane & 3;

    #pragma unroll
    for (int u = 0; u < 8; u++) {
        int f = tid + u * 256;
        int r = f >> 4, c = f & 15;
        float4 v = *(const float4*)(qkv + (size_t)(b*SEQ + q0 + r)*3*DMODEL + h*HDIM + c*4);
        float4 w;
        w.x = tf32r(v.x * 0.125f); w.y = tf32r(v.y * 0.125f);
        w.z = tf32r(v.z * 0.125f); w.w = tf32r(v.w * 0.125f);
        *(float4*)((char*)smf + att_off(r, c)) = w;
    }

    float m0 = -1e30f, m1 = -1e30f, l0 = 0.f, l1 = 0.f;
    float o[8][4];
    #pragma unroll
    for (int nb = 0; nb < 8; nb++)
        #pragma unroll
        for (int v = 0; v < 4; v++) o[nb][v] = 0.f;

    const int row0 = q0 + wq + qtr;

    for (int k0 = 0; k0 < q0 + 128; k0 += AT_KT) {
        __syncthreads();
        #pragma unroll
        for (int u = 0; u < 4; u++) {
            int f = tid + u * 256;
            int r = f >> 4, c = f & 15;
            float4 v = *(const float4*)(qkv + (size_t)(b*SEQ + k0 + r)*3*DMODEL + DMODEL + h*HDIM + c*4);
            float4 w;
            w.x = tf32r(v.x); w.y = tf32r(v.y); w.z = tf32r(v.z); w.w = tf32r(v.w);
            *(float4*)((char*)smf + 32768 + att_off(r, c)) = w;
        }
        #pragma unroll
        for (int u = 0; u < 4; u++) {
            int f = tid + u * 256;
            int kt = f >> 4, c = f & 15;
            float4 v = *(const float4*)(qkv + (size_t)(b*SEQ + k0 + kt)*3*DMODEL + 2*DMODEL + h*HDIM + c*4);
            float vv[4] = {v.x, v.y, v.z, v.w};
            #pragma unroll
            for (int j = 0; j < 4; j++) {
                int d = c * 4 + j;
                *(float*)((char*)smf + 49152 + att_off(d, kt >> 2) + (kt & 3) * 4) = tf32r(vv[j]);
            }
        }
        __syncthreads();

        float sc[8][4];
        #pragma unroll
        for (int nb = 0; nb < 8; nb++)
            #pragma unroll
            for (int v = 0; v < 4; v++) sc[nb][v] = 0.f;

        #pragma unroll
        for (int ks8 = 0; ks8 < 8; ks8++) {
            uint32_t af[4];
            LDSM_X4(af, qsB + att_off(wq + (lane & 15), 2*ks8 + (lane >> 4)));
            #pragma unroll
            for (int g = 0; g < 4; g++) {
                uint32_t r4[4];
                int n = g * 16 + (lane & 7) + ((lane >> 4) << 3);
                int ch = 2*ks8 + ((lane >> 3) & 1);
                LDSM_X4(r4, ksB + att_off(n, ch));
                uint32_t b0[2] = {r4[0], r4[1]};
                uint32_t b1[2] = {r4[2], r4[3]};
                MMA_TF32(sc[g*2    ], af, b0);
                MMA_TF32(sc[g*2 + 1], af, b1);
            }
        }

        if (k0 + AT_KT - 1 > q0 + wq) {
            #pragma unroll
            for (int nb = 0; nb < 8; nb++) {
                int c0 = k0 + nb*8 + qlc*2;
                if (c0     > row0    ) sc[nb][0] = -1e30f;
                if (c0 + 1 > row0    ) sc[nb][1] = -1e30f;
                if (c0     > row0 + 8) sc[nb][2] = -1e30f;
                if (c0 + 1 > row0 + 8) sc[nb][3] = -1e30f;
            }
        }

        float mx0 = sc[0][0], mx1 = sc[0][2];
        #pragma unroll
        for (int nb = 0; nb < 8; nb++) {
            mx0 = fmaxf(mx0, fmaxf(sc[nb][0], sc[nb][1]));
            mx1 = fmaxf(mx1, fmaxf(sc[nb][2], sc[nb][3]));
        }
        mx0 = fmaxf(mx0, __shfl_xor_sync(0xffffffffu, mx0, 1));
        mx0 = fmaxf(mx0, __shfl_xor_sync(0xffffffffu, mx0, 2));
        mx1 = fmaxf(mx1, __shfl_xor_sync(0xffffffffu, mx1, 1));
        mx1 = fmaxf(mx1, __shfl_xor_sync(0xffffffffu, mx1, 2));
        float nm0 = fmaxf(m0, mx0), nm1 = fmaxf(m1, mx1);
        float corr0 = fast_exp(m0 - nm0), corr1 = fast_exp(m1 - nm1);
        float s0 = 0.f, s1 = 0.f;
        #pragma unroll
        for (int nb = 0; nb < 8; nb++) {
            sc[nb][0] = fast_exp(sc[nb][0] - nm0);
            sc[nb][1] = fast_exp(sc[nb][1] - nm0);
            sc[nb][2] = fast_exp(sc[nb][2] - nm1);
            sc[nb][3] = fast_exp(sc[nb][3] - nm1);
            s0 += sc[nb][0] + sc[nb][1];
            s1 += sc[nb][2] + sc[nb][3];
        }
        s0 += __shfl_xor_sync(0xffffffffu, s0, 1);
        s0 += __shfl_xor_sync(0xffffffffu, s0, 2);
        s1 += __shfl_xor_sync(0xffffffffu, s1, 1);
        s1 += __shfl_xor_sync(0xffffffffu, s1, 2);
        l0 = l0 * corr0 + s0;  m0 = nm0;
        l1 = l1 * corr1 + s1;  m1 = nm1;
        #pragma unroll
        for (int nb = 0; nb < 8; nb++) {
            o[nb][0] *= corr0; o[nb][1] *= corr0;
            o[nb][2] *= corr1; o[nb][3] *= corr1;
        }

        int pr = wq + qtr;
        #pragma unroll
        for (int nb = 0; nb < 8; nb++) {
            int pc = nb*8 + qlc*2;
            Ps[pr*PS_STRIDE + pc    ] = tf32r(sc[nb][0]);
            Ps[pr*PS_STRIDE + pc + 1] = tf32r(sc[nb][1]);
            Ps[(pr+8)*PS_STRIDE + pc    ] = tf32r(sc[nb][2]);
            Ps[(pr+8)*PS_STRIDE + pc + 1] = tf32r(sc[nb][3]);
        }
        __syncwarp();

        #pragma unroll
        for (int ks8 = 0; ks8 < 8; ks8++) {
            uint32_t pa[4];
            int pk = ks8*8 + qlc;
            pa[0] = __float_as_uint(Ps[(wq + qtr    )*PS_STRIDE + pk    ]);
            pa[1] = __float_as_uint(Ps[(wq + qtr + 8)*PS_STRIDE + pk    ]);
            pa[2] = __float_as_uint(Ps[(wq + qtr    )*PS_STRIDE + pk + 4]);
            pa[3] = __float_as_uint(Ps[(wq + qtr + 8)*PS_STRIDE + pk + 4]);
            #pragma unroll
            for (int g = 0; g < 4; g++) {
                uint32_t r4[4];
                int n = g * 16 + (lane & 7) + ((lane >> 4) << 3);
                int ch = 2*ks8 + ((lane >> 3) & 1);
                LDSM_X4(r4, vtB + att_off(n, ch));
                uint32_t b0[2] = {r4[0], r4[1]};
                uint32_t b1[2] = {r4[2], r4[3]};
                MMA_TF32(o[g*2    ], pa, b0);
                MMA_TF32(o[g*2 + 1], pa, b1);
            }
        }
        __syncwarp();
    }

    // output feeds proj GEMM A -> tf32-pre-round
    float inv0 = 1.0f / l0, inv1 = 1.0f / l1;
    size_t g0 = (size_t)(b*SEQ + q0 + wq + qtr) * DMODEL + h*HDIM;
    size_t g1 = g0 + 8 * DMODEL;
    #pragma unroll
    for (int nb = 0; nb < 8; nb++) {
        int d0 = nb*8 + qlc*2;
        *(float2*)(y + g0 + d0) = make_float2(tf32r(o[nb][0]*inv0), tf32r(o[nb][1]*inv0));
        *(float2*)(y + g1 + d0) = make_float2(tf32r(o[nb][2]*inv1), tf32r(o[nb][3]*inv1));
    }
}

// ---------------- loss reduce over fused partials ----------------------------
__global__ void __launch_bounds__(256) rowloss2_k(const float* __restrict__ pm,
                                                  const float* __restrict__ ps,
                                                  const float* __restrict__ logits,
                                                  const int* __restrict__ tgt,
                                                  float* __restrict__ rowloss)
{
    int n = blockIdx.x;
    const float* rm = pm + (size_t)n * PCOLS;
    const float* rs = ps + (size_t)n * PCOLS;
    float m = -1e30f, ssum = 0.f;
    for (int i = threadIdx.x; i < PCOLS; i += 256) {
        float m2 = rm[i], s2 = rs[i];
        float M = fmaxf(m, m2);
        ssum = ssum*fast_exp(m - M) + s2*fast_exp(m2 - M);
        m = M;
    }
    #pragma unroll
    for (int o = 16; o; o >>= 1) {
        float m2 = __shfl_xor_sync(0xffffffffu, m, o);
        float s2 = __shfl_xor_sync(0xffffffffu, ssum, o);
        float M  = fmaxf(m, m2);
        ssum = ssum*fast_exp(m - M) + s2*fast_exp(m2 - M);
        m = M;
    }
    __shared__ float smm[8], sms[8];
    int wid = threadIdx.x >> 5;
    if ((threadIdx.x & 31) == 0) { smm[wid] = m; sms[wid] = ssum; }
    __syncthreads();
    if (threadIdx.x == 0) {
        float M = smm[0], S = sms[0];
        for (int i = 1; i < 8; i++) {
            float M2 = fmaxf(M, smm[i]);
            S = S*fast_exp(M - M2) + sms[i]*fast_exp(smm[i] - M2);
            M = M2;
        }
        float lse = M + logf(S);
        rowloss[n] = lse - logits[(size_t)n * VOCAB + tgt[n]];
    }
}

__global__ void finalize_k(const float* __restrict__ rowloss, float* __restrict__ out_loss)
{
    float s = 0.f;
    for (int i = threadIdx.x; i < NTOK; i += 256) s += rowloss[i];
    #pragma unroll
    for (int o = 16; o; o >>= 1) s += __shfl_xor_sync(0xffffffffu, s, o);
    __shared__ float sm[8];
    int wid = threadIdx.x >> 5;
    if ((threadIdx.x & 31) == 0) sm[wid] = s;
    __syncthreads();
    if (threadIdx.x == 0) {
        float t = 0.f;
        for (int i = 0; i < 8; i++) t += sm[i];
        *out_loss = t * (1.0f/NTOK);
    }
}

// ---------------- launch -----------------------------------------------------
extern "C" void kernel_launch(void* const* d_in, const int* in_sizes, int n_in,
                              void* d_out, int out_size)
{
    const int*   idx     = (const int*)  d_in[0];
    const int*   targets = (const int*)  d_in[1];
    const float* wte     = (const float*)d_in[2];
    const float* wpe     = (const float*)d_in[3];
    const float* ln1_w   = (const float*)d_in[4];
    const float* ln1_b   = (const float*)d_in[5];
    const float* attn_w  = (const float*)d_in[6];
    const float* attn_b  = (const float*)d_in[7];
    const float* proj_w  = (const float*)d_in[8];
    const float* proj_b  = (const float*)d_in[9];
    const float* ln2_w   = (const float*)d_in[10];
    const float* ln2_b   = (const float*)d_in[11];
    const float* fc_w    = (const float*)d_in[12];
    const float* fc_b    = (const float*)d_in[13];
    const float* fcp_w   = (const float*)d_in[14];
    const float* fcp_b   = (const float*)d_in[15];
    const float* lnf_w   = (const float*)d_in[16];
    const float* lnf_b   = (const float*)d_in[17];

    float *px, *ph, *pqkv, *patt, *pffn, *plogfb, *prl, *ppm, *pps;
    cudaGetSymbolAddress((void**)&px,    g_x);
    cudaGetSymbolAddress((void**)&ph,    g_h);
    cudaGetSymbolAddress((void**)&pqkv,  g_qkv);
    cudaGetSymbolAddress((void**)&patt,  g_att);
    cudaGetSymbolAddress((void**)&pffn,  g_ffn);
    cudaGetSymbolAddress((void**)&plogfb,g_logits_fallback);
    cudaGetSymbolAddress((void**)&prl,   g_rowloss);
    cudaGetSymbolAddress((void**)&ppm,   g_pm);
    cudaGetSymbolAddress((void**)&pps,   g_ps);

    static bool attr_done = false;
    if (!attr_done) {
        cudaFuncSetAttribute(gemm_tc<EPI_NONE>,  cudaFuncAttributeMaxDynamicSharedMemorySize, GT_SMEM);
        cudaFuncSetAttribute(gemm_tc<EPI_GELU>,  cudaFuncAttributeMaxDynamicSharedMemorySize, GT_SMEM);
        cudaFuncSetAttribute(gemm_tc<EPI_RESID>, cudaFuncAttributeMaxDynamicSharedMemorySize, GT_SMEM);
        cudaFuncSetAttribute(gemm_tc<EPI_LOSS>,  cudaFuncAttributeMaxDynamicSharedMemorySize, GT_SMEM);
        cudaFuncSetAttribute(attn_k, cudaFuncAttributeMaxDynamicSharedMemorySize, AT_SMEM);
        attr_done = true;
    }

    const long long LOGN = (long long)NTOK * VOCAB;
    float* logits_ptr;
    float* loss_ptr = nullptr;
    if ((long long)out_size >= LOGN) {
        logits_ptr = (float*)d_out;
        if ((long long)out_size > LOGN) loss_ptr = (float*)d_out + LOGN;
    } else {
        logits_ptr = plogfb;
        loss_ptr = (float*)d_out;
    }

    embed_k<<<NTOK, 256>>>(idx, wte, wpe, px);

    dim3 gq (3*DMODEL/128, NTOK/128);
    dim3 gp (DMODEL/128,   NTOK/128);
    dim3 gf (4*DMODEL/128, NTOK/128);
    dim3 gv (NVTILE, NTOK/128);
    dim3 ga (SEQ/128, BATCH*NHEAD);

    for (int l = 0; l < LAYERS; l++) {
        ln_k<<<NTOK, 256>>>(px, ln1_w + (size_t)l*DMODEL, ln1_b + (size_t)l*DMODEL, ph);
        gemm_tc<EPI_NONE><<<gq, 256, GT_SMEM>>>(ph, attn_w + (size_t)l*3*DMODEL*DMODEL,
                                       attn_b + (size_t)l*3*DMODEL, nullptr,
                                       pqkv, NTOK, 3*DMODEL, DMODEL, nullptr, nullptr);
        attn_k<<<ga, 256, AT_SMEM>>>(pqkv, patt);
        gemm_tc<EPI_RESID><<<gp, 256, GT_SMEM>>>(patt, proj_w + (size_t)l*DMODEL*DMODEL,
                                        proj_b + (size_t)l*DMODEL, px,
                                        px, NTOK, DMODEL, DMODEL, nullptr, nullptr);
        ln_k<<<NTOK, 256>>>(px, ln2_w + (size_t)l*DMODEL, ln2_b + (size_t)l*DMODEL, ph);
        gemm_tc<EPI_GELU><<<gf, 256, GT_SMEM>>>(ph, fc_w + (size_t)l*4*DMODEL*DMODEL,
                                       fc_b + (size_t)l*4*DMODEL, nullptr,
                                       pffn, NTOK, 4*DMODEL, DMODEL, nullptr, nullptr);
        gemm_tc<EPI_RESID><<<gp, 256, GT_SMEM>>>(pffn, fcp_w + (size_t)l*DMODEL*4*DMODEL,
                                        fcp_b + (size_t)l*DMODEL, px,
                                        px, NTOK, DMODEL, 4*DMODEL, nullptr, nullptr);
    }

    ln_k<<<NTOK, 256>>>(px, lnf_w, lnf_b, ph);
    gemm_tc<EPI_LOSS><<<gv, 256, GT_SMEM>>>(ph, wte, nullptr, nullptr,
                                   logits_ptr, NTOK, VOCAB, DMODEL, ppm, pps);

    if (loss_ptr) {
        rowloss2_k<<<NTOK, 256>>>(ppm, pps, logits_ptr, targets, prl);
        finalize_k<<<1, 256>>>(prl, loss_ptr);
    }
}

// round 7
// speedup vs baseline: 4.8103x; 1.0351x over previous
#include <cuda_runtime.h>
#include <math.h>
#include <stdint.h>

// Problem constants
#define LAYERS 6
#define NHEAD  16
#define DMODEL 1024
#define HDIM   64
#define BATCH  2
#define SEQ    1024
#define NTOK   (BATCH*SEQ)     // 2048
#define VOCAB  50257
#define NVTILE ((VOCAB+127)/128)     // 393
#define PCOLS  (NVTILE*4)            // 1572 loss partials per row

// ---------------- scratch ----------------------------------------------------
__device__ float g_x   [NTOK*DMODEL];
__device__ float g_h   [NTOK*DMODEL];
__device__ float g_qkv [NTOK*3*DMODEL];
__device__ float g_att [NTOK*DMODEL];
__device__ float g_ffn [NTOK*4*DMODEL];
__device__ float g_logits_fallback[(size_t)NTOK*VOCAB];
__device__ float g_rowloss[NTOK];
__device__ float g_pm[(size_t)NTOK*PCOLS];
__device__ float g_ps[(size_t)NTOK*PCOLS];

// ---------------- PTX helpers (sm_80-portable only) --------------------------
__device__ __forceinline__ uint32_t smem_to_u32(const void* p) {
    uint32_t a;
    asm("{ .reg .u64 t; cvta.to.shared.u64 t, %1; cvt.u32.u64 %0, t; }" : "=r"(a) : "l"(p));
    return a;
}
__device__ __forceinline__ void cp_async16(uint32_t dst, const void* src, int srcsize) {
    asm volatile("cp.async.cg.shared.global [%0], [%1], 16, %2;\n"
                 :: "r"(dst), "l"(src), "r"(srcsize) : "memory");
}
#define CP_COMMIT() asm volatile("cp.async.commit_group;" ::: "memory")

#define LDSM_X4(r, a) \
    asm volatile("ldmatrix.sync.aligned.m8n8.x4.shared.b16 {%0,%1,%2,%3}, [%4];" \
        : "=r"((r)[0]), "=r"((r)[1]), "=r"((r)[2]), "=r"((r)[3]) : "r"(a))

#define MMA_TF32(d, a, b) \
    asm volatile("mma.sync.aligned.m16n8k8.row.col.f32.tf32.tf32.f32 " \
        "{%0,%1,%2,%3}, {%4,%5,%6,%7}, {%8,%9}, {%0,%1,%2,%3};" \
        : "+f"((d)[0]), "+f"((d)[1]), "+f"((d)[2]), "+f"((d)[3]) \
        : "r"((a)[0]), "r"((a)[1]), "r"((a)[2]), "r"((a)[3]), "r"((b)[0]), "r"((b)[1]))

__device__ __forceinline__ uint32_t cvt_tf32(uint32_t x) {
    uint32_t y;
    asm("cvt.rna.tf32.f32 %0, %1;" : "=r"(y) : "f"(__uint_as_float(x)));
    return y;
}
__device__ __forceinline__ float tf32r(float x) {
    uint32_t y;
    asm("cvt.rna.tf32.f32 %0, %1;" : "=r"(y) : "f"(x));
    return __uint_as_float(y);
}

// MUFU-free exp (B300 MUFU is ~0.5 op/cyc/SM): magic-number 2^n split + deg-5 poly.
__device__ __forceinline__ float fast_exp(float x) {
    x = fmaxf(x, -87.0f);
    float f = fminf(x * 1.44269504088896341f, 126.0f);
    float t = f + 12582912.0f;                 // 2^23 + 2^22
    int bits = __float_as_int(t);
    int n = (bits & 0x007FFFFF) - 0x00400000;
    float r = f - (t - 12582912.0f);           // r in [-0.5, 0.5]
    float p = 1.33335581e-3f;
    p = p * r + 9.61812911e-3f;
    p = p * r + 5.55041087e-2f;
    p = p * r + 2.40226507e-1f;
    p = p * r + 6.93147181e-1f;
    p = p * r + 1.0f;
    return p * __int_as_float((n + 127) << 23);
}

// ---------------- tf32 mma.sync NT GEMM: C[M,N] = A[M,K]*B[N,K]^T (+epi) -----
// A operands are produced tf32-pre-rounded by our own kernels -> no A cvts.
// SWAP=1: blockIdx.x indexes M-tiles, blockIdx.y indexes N-tiles (so that
// concurrent CTAs share B tiles -> B streamed from DRAM once; used for lm-head).
enum { EPI_NONE = 0, EPI_GELU = 1, EPI_RESID = 2, EPI_LOSS = 3 };

#define GBM 128
#define GBK 32
#define GSTAGES 3
#define GSTAGE_BYTES (GBM*GBK*4)                 // 16384
#define GT_SMEM (1024 + 2*GSTAGES*GSTAGE_BYTES)  // 99328

__device__ __forceinline__ uint32_t sw_off(int r, int c) {
    return (uint32_t)(r * 128 + ((c ^ (r & 7)) << 4));
}

template<int EPI, int SWAP>
__global__ void __launch_bounds__(256, 2) gemm_tc(
    const float* __restrict__ A, const float* __restrict__ B,
    const float* __restrict__ bias, const float* __restrict__ Rres,
    float* __restrict__ C, int M, int N, int K,
    float* __restrict__ Pm, float* __restrict__ Psum)
{
    extern __shared__ char dsm[];
    const int tid  = threadIdx.x;
    const int wid  = tid >> 5;
    const int lane = tid & 31;
    const int wm = wid >> 2;
    const int wn = wid & 3;
    const int bm = (SWAP ? blockIdx.x : blockIdx.y) * 128;
    const int bn = (SWAP ? blockIdx.y : blockIdx.x) * 128;
    const int ntile = SWAP ? blockIdx.y : blockIdx.x;

    uint32_t sbase = (smem_to_u32(dsm) + 1023u) & ~1023u;
    uint32_t aStage0 = sbase;
    uint32_t bStage0 = sbase + GSTAGES * GSTAGE_BYTES;

    const int T = K / GBK;

    auto load_tile = [&](int kt, int slot) {
        int k0 = kt * GBK;
        uint32_t aB = aStage0 + slot * GSTAGE_BYTES;
        uint32_t bB = bStage0 + slot * GSTAGE_BYTES;
        #pragma unroll
        for (int u = 0; u < 4; u++) {
            int f = tid + u * 256;
            int r = f >> 3, c = f & 7;
            cp_async16(aB + sw_off(r, c), A + (size_t)(bm + r) * K + k0 + c * 4, 16);
            int gb = bn + r;
            const float* bsrc = B + (size_t)(gb < N ? gb : 0) * K + k0 + c * 4;
            cp_async16(bB + sw_off(r, c), bsrc, gb < N ? 16 : 0);
        }
        CP_COMMIT();
    };

    float acc[4][4][4];
    #pragma unroll
    for (int i = 0; i < 4; i++)
        #pragma unroll
        for (int j = 0; j < 4; j++)
            #pragma unroll
            for (int v = 0; v < 4; v++) acc[i][j][v] = 0.f;

    load_tile(0, 0);
    load_tile(1, 1);
    load_tile(2, 2);

    for (int kt = 0; kt < T; kt++) {
        if (kt < T - 2)       asm volatile("cp.async.wait_group 2;" ::: "memory");
        else if (kt == T - 2) asm volatile("cp.async.wait_group 1;" ::: "memory");
        else                  asm volatile("cp.async.wait_group 0;" ::: "memory");
        __syncthreads();

        int slot = kt % GSTAGES;
        uint32_t aS = aStage0 + slot * GSTAGE_BYTES;
        uint32_t bS = bStage0 + slot * GSTAGE_BYTES;

        #pragma unroll
        for (int kk = 0; kk < 4; kk++) {
            uint32_t af[4][4];
            uint32_t bf[4][2];
            #pragma unroll
            for (int mb = 0; mb < 4; mb++) {
                int row = wm * 64 + mb * 16 + (lane & 15);
                int chunk = kk * 2 + (lane >> 4);
                LDSM_X4(af[mb], aS + row * 128 + ((chunk ^ (row & 7)) << 4));
            }
            #pragma unroll
            for (int p = 0; p < 2; p++) {
                uint32_t r4[4];
                int n = wn * 32 + p * 16 + (lane & 7) + ((lane >> 4) << 3);
                int chunk = kk * 2 + ((lane >> 3) & 1);
                LDSM_X4(r4, bS + n * 128 + ((chunk ^ (n & 7)) << 4));
                bf[p*2  ][0] = r4[0]; bf[p*2  ][1] = r4[1];
                bf[p*2+1][0] = r4[2]; bf[p*2+1][1] = r4[3];
            }
            // A pre-rounded by producer; only B (raw weights) needs rounding.
            #pragma unroll
            for (int nb = 0; nb < 4; nb++) {
                bf[nb][0] = cvt_tf32(bf[nb][0]);
                bf[nb][1] = cvt_tf32(bf[nb][1]);
            }
            #pragma unroll
            for (int mb = 0; mb < 4; mb++)
                #pragma unroll
                for (int nb = 0; nb < 4; nb++)
                    MMA_TF32(acc[mb][nb], af[mb], bf[nb]);
        }
        __syncthreads();
        if (kt + GSTAGES < T) load_tile(kt + GSTAGES, slot);
    }

    if (EPI == EPI_LOSS) {
        // store logits + per-warp (max, sumexp) partials for the loss
        #pragma unroll
        for (int mb = 0; mb < 4; mb++) {
            #pragma unroll
            for (int half = 0; half < 2; half++) {
                int rrow = bm + wm * 64 + mb * 16 + (lane >> 2) + half * 8;
                float vals[8];
                float vmax = -1e30f;
                #pragma unroll
                for (int nb = 0; nb < 4; nb++) {
                    int col = bn + wn * 32 + nb * 8 + (lane & 3) * 2;
                    float v0 = acc[mb][nb][half*2 + 0];
                    float v1 = acc[mb][nb][half*2 + 1];
                    size_t base = (size_t)rrow * N + col;
                    if (col + 1 < N) {
                        if ((base & 1) == 0) *(float2*)(C + base) = make_float2(v0, v1);
                        else { C[base] = v0; C[base + 1] = v1; }
                    } else if (col < N) {
                        C[base] = v0;
                    }
                    vals[nb*2    ] = (col     < N) ? v0 : -1e30f;
                    vals[nb*2 + 1] = (col + 1 < N) ? v1 : -1e30f;
                    vmax = fmaxf(vmax, fmaxf(vals[nb*2], vals[nb*2+1]));
                }
                vmax = fmaxf(vmax, __shfl_xor_sync(0xffffffffu, vmax, 1));
                vmax = fmaxf(vmax, __shfl_xor_sync(0xffffffffu, vmax, 2));
                float s = 0.f;
                #pragma unroll
                for (int j = 0; j < 8; j++) s += fast_exp(vals[j] - vmax);
                s += __shfl_xor_sync(0xffffffffu, s, 1);
                s += __shfl_xor_sync(0xffffffffu, s, 2);
                if ((lane & 3) == 0) {
                    size_t po = (size_t)rrow * PCOLS + ntile * 4 + wn;
                    Pm[po] = vmax;
                    Psum[po] = s;
                }
            }
        }
        return;
    }

    // generic epilogue (alignment-safe: N may be odd)
    #pragma unroll
    for (int mb = 0; mb < 4; mb++) {
        int r0 = bm + wm * 64 + mb * 16 + (lane >> 2);
        #pragma unroll
        for (int nb = 0; nb < 4; nb++) {
            int col = bn + wn * 32 + nb * 8 + (lane & 3) * 2;
            #pragma unroll
            for (int half = 0; half < 2; half++) {
                size_t row = (size_t)(r0 + half * 8);
                float v0 = acc[mb][nb][half*2 + 0];
                float v1 = acc[mb][nb][half*2 + 1];
                size_t base = row * (size_t)N + col;
                if (col + 1 < N) {
                    if (bias) { v0 += bias[col]; v1 += bias[col+1]; }
                    if (EPI == EPI_GELU) {
                        v0 = tf32r(0.5f*v0*(1.0f + erff(v0*0.70710678118654752f)));
                        v1 = tf32r(0.5f*v1*(1.0f + erff(v1*0.70710678118654752f)));
                    }
                    if (EPI == EPI_RESID) {
                        if ((base & 1) == 0) {
                            float2 rr = *(const float2*)(Rres + base);
                            v0 += rr.x; v1 += rr.y;
                        } else {
                            v0 += Rres[base]; v1 += Rres[base + 1];
                        }
                    }
                    if ((base & 1) == 0) {
                        *(float2*)(C + base) = make_float2(v0, v1);
                    } else {
                        C[base] = v0; C[base + 1] = v1;
                    }
                } else if (col < N) {
                    if (bias) v0 += bias[col];
                    if (EPI == EPI_GELU) v0 = tf32r(0.5f*v0*(1.0f + erff(v0*0.70710678118654752f)));
                    if (EPI == EPI_RESID) v0 += Rres[base];
                    C[base] = v0;
                }
            }
        }
    }
}

// ---------------- embedding --------------------------------------------------
__global__ void embed_k(const int* __restrict__ idx,
                        const float* __restrict__ wte,
                        const float* __restrict__ wpe,
                        float* __restrict__ x)
{
    int n = blockIdx.x;
    int tok = idx[n];
    int t = n % SEQ;
    const float4* a = (const float4*)(wte + (size_t)tok * DMODEL);
    const float4* p = (const float4*)(wpe + (size_t)t   * DMODEL);
    float4* o = (float4*)(x + (size_t)n * DMODEL);
    for (int i = threadIdx.x; i < DMODEL/4; i += blockDim.x) {
        float4 u = a[i], v = p[i];
        o[i] = make_float4(u.x+v.x, u.y+v.y, u.z+v.z, u.w+v.w);
    }
}

// ---------------- layernorm (output tf32-pre-rounded: it only feeds GEMM A) --
__global__ void __launch_bounds__(256) ln_k(const float* __restrict__ x,
                                            const float* __restrict__ w,
                                            const float* __restrict__ b,
                                            float* __restrict__ out)
{
    int n = blockIdx.x;
    const float* row = x + (size_t)n * DMODEL;
    float s = 0.f, ss = 0.f;
    for (int i = threadIdx.x; i < DMODEL/4; i += 256) {
        float4 v = ((const float4*)row)[i];
        s  += v.x + v.y + v.z + v.w;
        ss += v.x*v.x + v.y*v.y + v.z*v.z + v.w*v.w;
    }
    #pragma unroll
    for (int o = 16; o; o >>= 1) {
        s  += __shfl_xor_sync(0xffffffffu, s,  o);
        ss += __shfl_xor_sync(0xffffffffu, ss, o);
    }
    __shared__ float sm[8], sm2[8];
    int wid = threadIdx.x >> 5;
    if ((threadIdx.x & 31) == 0) { sm[wid] = s; sm2[wid] = ss; }
    __syncthreads();
    if (threadIdx.x < 32) {
        s  = (threadIdx.x < 8) ? sm [threadIdx.x] : 0.f;
        ss = (threadIdx.x < 8) ? sm2[threadIdx.x] : 0.f;
        #pragma unroll
        for (int o = 4; o; o >>= 1) {
            s  += __shfl_xor_sync(0xffffffffu, s,  o);
            ss += __shfl_xor_sync(0xffffffffu, ss, o);
        }
        if (threadIdx.x == 0) { sm[0] = s; sm2[0] = ss; }
    }
    __syncthreads();
    float mean = sm[0] * (1.0f/DMODEL);
    float var  = sm2[0] * (1.0f/DMODEL) - mean*mean;
    float inv  = rsqrtf(var + 1e-5f);
    float* orow = out + (size_t)n * DMODEL;
    for (int i = threadIdx.x; i < DMODEL/4; i += 256) {
        float4 v  = ((const float4*)row)[i];
        float4 gw = ((const float4*)w)[i];
        float4 gb = ((const float4*)b)[i];
        float4 r;
        r.x = tf32r((v.x - mean)*inv*gw.x + gb.x);
        r.y = tf32r((v.y - mean)*inv*gw.y + gb.y);
        r.z = tf32r((v.z - mean)*inv*gw.z + gb.z);
        r.w = tf32r((v.w - mean)*inv*gw.w + gb.w);
        ((float4*)orow)[i] = r;
    }
}

// ---------------- tensor-core flash attention --------------------------------
// 128 threads (4 warps), Q tile 64, K tile 64 -> 65KB smem, 3 CTAs/SM, 512 CTAs.
// smem: Qs 16384 | Ks 16384 | VT 16384 | Ps 64*68*4=17408 => 66560 bytes
#define AT_KT 64
#define AT_SMEM 66560
#define PS_STRIDE 68

__device__ __forceinline__ uint32_t att_off(int r, int c /*16B chunk 0..15*/) {
    return (uint32_t)(r * 256 + ((c & 8) << 4) + (((c & 7) ^ (r & 7)) << 4));
}

__global__ void __launch_bounds__(128) attn_k(const float* __restrict__ qkv,
                                              float* __restrict__ y)
{
    extern __shared__ float smf[];
    uint32_t qsB = smem_to_u32(smf);
    uint32_t ksB = qsB + 16384;
    uint32_t vtB = qsB + 32768;
    float* Ps = smf + 12288;            // byte offset 49152

    const int bh = blockIdx.y;
    const int b = bh >> 4, h = bh & 15;
    const int q0 = (gridDim.x - 1 - blockIdx.x) * 64;   // heavy tiles first
    const int tid = threadIdx.x, wid = tid >> 5, lane = tid & 31;
    const int wq = wid * 16;
    const int qtr = lane >> 2;
    const int qlc = lane & 3;

    // Q tile: 64 rows x 64 floats (scaled 1/8, tf32-rounded), swizzled
    #pragma unroll
    for (int u = 0; u < 8; u++) {
        int f = tid + u * 128;
        int r = f >> 4, c = f & 15;
        float4 v = *(const float4*)(qkv + (size_t)(b*SEQ + q0 + r)*3*DMODEL + h*HDIM + c*4);
        float4 w;
        w.x = tf32r(v.x * 0.125f); w.y = tf32r(v.y * 0.125f);
        w.z = tf32r(v.z * 0.125f); w.w = tf32r(v.w * 0.125f);
        *(float4*)((char*)smf + att_off(r, c)) = w;
    }

    float m0 = -1e30f, m1 = -1e30f, l0 = 0.f, l1 = 0.f;
    float o[8][4];
    #pragma unroll
    for (int nb = 0; nb < 8; nb++)
        #pragma unroll
        for (int v = 0; v < 4; v++) o[nb][v] = 0.f;

    const int row0 = q0 + wq + qtr;

    for (int k0 = 0; k0 < q0 + 64; k0 += AT_KT) {
        __syncthreads();
        // K tile
        #pragma unroll
        for (int u = 0; u < 8; u++) {
            int f = tid + u * 128;
            int r = f >> 4, c = f & 15;
            float4 v = *(const float4*)(qkv + (size_t)(b*SEQ + k0 + r)*3*DMODEL + DMODEL + h*HDIM + c*4);
            float4 w;
            w.x = tf32r(v.x); w.y = tf32r(v.y); w.z = tf32r(v.z); w.w = tf32r(v.w);
            *(float4*)((char*)smf + 16384 + att_off(r, c)) = w;
        }
        // V^T tile (transpose scatter)
        #pragma unroll
        for (int u = 0; u < 8; u++) {
            int f = tid + u * 128;
            int kt = f >> 4, c = f & 15;
            float4 v = *(const float4*)(qkv + (size_t)(b*SEQ + k0 + kt)*3*DMODEL + 2*DMODEL + h*HDIM + c*4);
            float vv[4] = {v.x, v.y, v.z, v.w};
            #pragma unroll
            for (int j = 0; j < 4; j++) {
                int d = c * 4 + j;
                *(float*)((char*)smf + 32768 + att_off(d, kt >> 2) + (kt & 3) * 4) = tf32r(vv[j]);
            }
        }
        __syncthreads();

        float sc[8][4];
        #pragma unroll
        for (int nb = 0; nb < 8; nb++)
            #pragma unroll
            for (int v = 0; v < 4; v++) sc[nb][v] = 0.f;

        #pragma unroll
        for (int ks8 = 0; ks8 < 8; ks8++) {
            uint32_t af[4];
            LDSM_X4(af, qsB + att_off(wq + (lane & 15), 2*ks8 + (lane >> 4)));
            #pragma unroll
            for (int g = 0; g < 4; g++) {
                uint32_t r4[4];
                int n = g * 16 + (lane & 7) + ((lane >> 4) << 3);
                int ch = 2*ks8 + ((lane >> 3) & 1);
                LDSM_X4(r4, ksB + att_off(n, ch));
                uint32_t b0[2] = {r4[0], r4[1]};
                uint32_t b1[2] = {r4[2], r4[3]};
                MMA_TF32(sc[g*2    ], af, b0);
                MMA_TF32(sc[g*2 + 1], af, b1);
            }
        }

        if (k0 + AT_KT - 1 > q0 + wq) {
            #pragma unroll
            for (int nb = 0; nb < 8; nb++) {
                int c0 = k0 + nb*8 + qlc*2;
                if (c0     > row0    ) sc[nb][0] = -1e30f;
                if (c0 + 1 > row0    ) sc[nb][1] = -1e30f;
                if (c0     > row0 + 8) sc[nb][2] = -1e30f;
                if (c0 + 1 > row0 + 8) sc[nb][3] = -1e30f;
            }
        }

        float mx0 = sc[0][0], mx1 = sc[0][2];
        #pragma unroll
        for (int nb = 0; nb < 8; nb++) {
            mx0 = fmaxf(mx0, fmaxf(sc[nb][0], sc[nb][1]));
            mx1 = fmaxf(mx1, fmaxf(sc[nb][2], sc[nb][3]));
        }
        mx0 = fmaxf(mx0, __shfl_xor_sync(0xffffffffu, mx0, 1));
        mx0 = fmaxf(mx0, __shfl_xor_sync(0xffffffffu, mx0, 2));
        mx1 = fmaxf(mx1, __shfl_xor_sync(0xffffffffu, mx1, 1));
        mx1 = fmaxf(mx1, __shfl_xor_sync(0xffffffffu, mx1, 2));
        float nm0 = fmaxf(m0, mx0), nm1 = fmaxf(m1, mx1);
        float corr0 = fast_exp(m0 - nm0), corr1 = fast_exp(m1 - nm1);
        float s0 = 0.f, s1 = 0.f;
        #pragma unroll
        for (int nb = 0; nb < 8; nb++) {
            sc[nb][0] = fast_exp(sc[nb][0] - nm0);
            sc[nb][1] = fast_exp(sc[nb][1] - nm0);
            sc[nb][2] = fast_exp(sc[nb][2] - nm1);
            sc[nb][3] = fast_exp(sc[nb][3] - nm1);
            s0 += sc[nb][0] + sc[nb][1];
            s1 += sc[nb][2] + sc[nb][3];
        }
        s0 += __shfl_xor_sync(0xffffffffu, s0, 1);
        s0 += __shfl_xor_sync(0xffffffffu, s0, 2);
        s1 += __shfl_xor_sync(0xffffffffu, s1, 1);
        s1 += __shfl_xor_sync(0xffffffffu, s1, 2);
        l0 = l0 * corr0 + s0;  m0 = nm0;
        l1 = l1 * corr1 + s1;  m1 = nm1;
        #pragma unroll
        for (int nb = 0; nb < 8; nb++) {
            o[nb][0] *= corr0; o[nb][1] *= corr0;
            o[nb][2] *= corr1; o[nb][3] *= corr1;
        }

        int pr = wq + qtr;
        #pragma unroll
        for (int nb = 0; nb < 8; nb++) {
            int pc = nb*8 + qlc*2;
            Ps[pr*PS_STRIDE + pc    ] = tf32r(sc[nb][0]);
            Ps[pr*PS_STRIDE + pc + 1] = tf32r(sc[nb][1]);
            Ps[(pr+8)*PS_STRIDE + pc    ] = tf32r(sc[nb][2]);
            Ps[(pr+8)*PS_STRIDE + pc + 1] = tf32r(sc[nb][3]);
        }
        __syncwarp();

        #pragma unroll
        for (int ks8 = 0; ks8 < 8; ks8++) {
            uint32_t pa[4];
            int pk = ks8*8 + qlc;
            pa[0] = __float_as_uint(Ps[(wq + qtr    )*PS_STRIDE + pk    ]);
            pa[1] = __float_as_uint(Ps[(wq + qtr + 8)*PS_STRIDE + pk    ]);
            pa[2] = __float_as_uint(Ps[(wq + qtr    )*PS_STRIDE + pk + 4]);
            pa[3] = __float_as_uint(Ps[(wq + qtr + 8)*PS_STRIDE + pk + 4]);
            #pragma unroll
            for (int g = 0; g < 4; g++) {
                uint32_t r4[4];
                int n = g * 16 + (lane & 7) + ((lane >> 4) << 3);
                int ch = 2*ks8 + ((lane >> 3) & 1);
                LDSM_X4(r4, vtB + att_off(n, ch));
                uint32_t b0[2] = {r4[0], r4[1]};
                uint32_t b1[2] = {r4[2], r4[3]};
                MMA_TF32(o[g*2    ], pa, b0);
                MMA_TF32(o[g*2 + 1], pa, b1);
            }
        }
        __syncwarp();
    }

    // output feeds proj GEMM A -> tf32-pre-round
    float inv0 = 1.0f / l0, inv1 = 1.0f / l1;
    size_t g0 = (size_t)(b*SEQ + q0 + wq + qtr) * DMODEL + h*HDIM;
    size_t g1 = g0 + 8 * DMODEL;
    #pragma unroll
    for (int nb = 0; nb < 8; nb++) {
        int d0 = nb*8 + qlc*2;
        *(float2*)(y + g0 + d0) = make_float2(tf32r(o[nb][0]*inv0), tf32r(o[nb][1]*inv0));
        *(float2*)(y + g1 + d0) = make_float2(tf32r(o[nb][2]*inv1), tf32r(o[nb][3]*inv1));
    }
}

// ---------------- loss reduce over fused partials ----------------------------
__global__ void __launch_bounds__(256) rowloss2_k(const float* __restrict__ pm,
                                                  const float* __restrict__ ps,
                                                  const float* __restrict__ logits,
                                                  const int* __restrict__ tgt,
                                                  float* __restrict__ rowloss)
{
    int n = blockIdx.x;
    const float* rm = pm + (size_t)n * PCOLS;
    const float* rs = ps + (size_t)n * PCOLS;
    float m = -1e30f, ssum = 0.f;
    for (int i = threadIdx.x; i < PCOLS; i += 256) {
        float m2 = rm[i], s2 = rs[i];
        float M = fmaxf(m, m2);
        ssum = ssum*fast_exp(m - M) + s2*fast_exp(m2 - M);
        m = M;
    }
    #pragma unroll
    for (int o = 16; o; o >>= 1) {
        float m2 = __shfl_xor_sync(0xffffffffu, m, o);
        float s2 = __shfl_xor_sync(0xffffffffu, ssum, o);
        float M  = fmaxf(m, m2);
        ssum = ssum*fast_exp(m - M) + s2*fast_exp(m2 - M);
        m = M;
    }
    __shared__ float smm[8], sms[8];
    int wid = threadIdx.x >> 5;
    if ((threadIdx.x & 31) == 0) { smm[wid] = m; sms[wid] = ssum; }
    __syncthreads();
    if (threadIdx.x == 0) {
        float M = smm[0], S = sms[0];
        for (int i = 1; i < 8; i++) {
            float M2 = fmaxf(M, smm[i]);
            S = S*fast_exp(M - M2) + sms[i]*fast_exp(smm[i] - M2);
            M = M2;
        }
        float lse = M + logf(S);
        rowloss[n] = lse - logits[(size_t)n * VOCAB + tgt[n]];
    }
}

__global__ void finalize_k(const float* __restrict__ rowloss, float* __restrict__ out_loss)
{
    float s = 0.f;
    for (int i = threadIdx.x; i < NTOK; i += 256) s += rowloss[i];
    #pragma unroll
    for (int o = 16; o; o >>= 1) s += __shfl_xor_sync(0xffffffffu, s, o);
    __shared__ float sm[8];
    int wid = threadIdx.x >> 5;
    if ((threadIdx.x & 31) == 0) sm[wid] = s;
    __syncthreads();
    if (threadIdx.x == 0) {
        float t = 0.f;
        for (int i = 0; i < 8; i++) t += sm[i];
        *out_loss = t * (1.0f/NTOK);
    }
}

// ---------------- launch -----------------------------------------------------
extern "C" void kernel_launch(void* const* d_in, const int* in_sizes, int n_in,
                              void* d_out, int out_size)
{
    const int*   idx     = (const int*)  d_in[0];
    const int*   targets = (const int*)  d_in[1];
    const float* wte     = (const float*)d_in[2];
    const float* wpe     = (const float*)d_in[3];
    const float* ln1_w   = (const float*)d_in[4];
    const float* ln1_b   = (const float*)d_in[5];
    const float* attn_w  = (const float*)d_in[6];
    const float* attn_b  = (const float*)d_in[7];
    const float* proj_w  = (const float*)d_in[8];
    const float* proj_b  = (const float*)d_in[9];
    const float* ln2_w   = (const float*)d_in[10];
    const float* ln2_b   = (const float*)d_in[11];
    const float* fc_w    = (const float*)d_in[12];
    const float* fc_b    = (const float*)d_in[13];
    const float* fcp_w   = (const float*)d_in[14];
    const float* fcp_b   = (const float*)d_in[15];
    const float* lnf_w   = (const float*)d_in[16];
    const float* lnf_b   = (const float*)d_in[17];

    float *px, *ph, *pqkv, *patt, *pffn, *plogfb, *prl, *ppm, *pps;
    cudaGetSymbolAddress((void**)&px,    g_x);
    cudaGetSymbolAddress((void**)&ph,    g_h);
    cudaGetSymbolAddress((void**)&pqkv,  g_qkv);
    cudaGetSymbolAddress((void**)&patt,  g_att);
    cudaGetSymbolAddress((void**)&pffn,  g_ffn);
    cudaGetSymbolAddress((void**)&plogfb,g_logits_fallback);
    cudaGetSymbolAddress((void**)&prl,   g_rowloss);
    cudaGetSymbolAddress((void**)&ppm,   g_pm);
    cudaGetSymbolAddress((void**)&pps,   g_ps);

    static bool attr_done = false;
    if (!attr_done) {
        cudaFuncSetAttribute((const void*)gemm_tc<EPI_NONE,0>,  cudaFuncAttributeMaxDynamicSharedMemorySize, GT_SMEM);
        cudaFuncSetAttribute((const void*)gemm_tc<EPI_GELU,0>,  cudaFuncAttributeMaxDynamicSharedMemorySize, GT_SMEM);
        cudaFuncSetAttribute((const void*)gemm_tc<EPI_RESID,0>, cudaFuncAttributeMaxDynamicSharedMemorySize, GT_SMEM);
        cudaFuncSetAttribute((const void*)gemm_tc<EPI_LOSS,1>,  cudaFuncAttributeMaxDynamicSharedMemorySize, GT_SMEM);
        cudaFuncSetAttribute((const void*)attn_k, cudaFuncAttributeMaxDynamicSharedMemorySize, AT_SMEM);
        attr_done = true;
    }

    const long long LOGN = (long long)NTOK * VOCAB;
    float* logits_ptr;
    float* loss_ptr = nullptr;
    if ((long long)out_size >= LOGN) {
        logits_ptr = (float*)d_out;
        if ((long long)out_size > LOGN) loss_ptr = (float*)d_out + LOGN;
    } else {
        logits_ptr = plogfb;
        loss_ptr = (float*)d_out;
    }

    embed_k<<<NTOK, 256>>>(idx, wte, wpe, px);

    dim3 gq (3*DMODEL/128, NTOK/128);
    dim3 gp (DMODEL/128,   NTOK/128);
    dim3 gf (4*DMODEL/128, NTOK/128);
    dim3 gv (NTOK/128, NVTILE);          // SWAP=1: x=M-tiles, y=N-tiles (B reuse)
    dim3 ga (SEQ/64, BATCH*NHEAD);

    for (int l = 0; l < LAYERS; l++) {
        ln_k<<<NTOK, 256>>>(px, ln1_w + (size_t)l*DMODEL, ln1_b + (size_t)l*DMODEL, ph);
        gemm_tc<EPI_NONE,0><<<gq, 256, GT_SMEM>>>(ph, attn_w + (size_t)l*3*DMODEL*DMODEL,
                                       attn_b + (size_t)l*3*DMODEL, nullptr,
                                       pqkv, NTOK, 3*DMODEL, DMODEL, nullptr, nullptr);
        attn_k<<<ga, 128, AT_SMEM>>>(pqkv, patt);
        gemm_tc<EPI_RESID,0><<<gp, 256, GT_SMEM>>>(patt, proj_w + (size_t)l*DMODEL*DMODEL,
                                        proj_b + (size_t)l*DMODEL, px,
                                        px, NTOK, DMODEL, DMODEL, nullptr, nullptr);
        ln_k<<<NTOK, 256>>>(px, ln2_w + (size_t)l*DMODEL, ln2_b + (size_t)l*DMODEL, ph);
        gemm_tc<EPI_GELU,0><<<gf, 256, GT_SMEM>>>(ph, fc_w + (size_t)l*4*DMODEL*DMODEL,
                                       fc_b + (size_t)l*4*DMODEL, nullptr,
                                       pffn, NTOK, 4*DMODEL, DMODEL, nullptr, nullptr);
        gemm_tc<EPI_RESID,0><<<gp, 256, GT_SMEM>>>(pffn, fcp_w + (size_t)l*DMODEL*4*DMODEL,
                                        fcp_b + (size_t)l*DMODEL, px,
                                        px, NTOK, DMODEL, 4*DMODEL, nullptr, nullptr);
    }

    ln_k<<<NTOK, 256>>>(px, lnf_w, lnf_b, ph);
    gemm_tc<EPI_LOSS,1><<<gv, 256, GT_SMEM>>>(ph, wte, nullptr, nullptr,
                                   logits_ptr, NTOK, VOCAB, DMODEL, ppm, pps);

    if (loss_ptr) {
        rowloss2_k<<<NTOK, 256>>>(ppm, pps, logits_ptr, targets, prl);
        finalize_k<<<1, 256>>>(prl, loss_ptr);
    }
}